// round 14
// baseline (speedup 1.0000x reference)
#include <cuda_runtime.h>
#include <cuda_fp16.h>
#include <stdint.h>

#define DI __device__ __forceinline__

// ===================== device scratch (no allocations) =====================
__device__ float g_Upp[128*64*128];
__device__ float g_Vpp[128*64*128];
__device__ float g_Upv[128*64*128];
__device__ float g_Vpv[128*14*128];
__device__ float g_EppT[128*64*64];   // transposed: [b][c][r]
__device__ float g_EpvT[128*64*64];   // transposed: [b][c][r]

// pre-transposed fp16 weight images, pp16-permuted k, stride 144 halves (176 for FO1)
__device__ __align__(16) __half g_W2pp[128*144];
__device__ __align__(16) __half g_W3pp[64*144];
__device__ __align__(16) __half g_W2pv[128*144];
__device__ __align__(16) __half g_W3pv[64*144];
__device__ __align__(16) __half g_FO1 [128*176];
__device__ __align__(16) __half g_FO2 [128*144];
__device__ __align__(16) __half g_FO3 [64*144];

// ===================== helpers =====================
DI int pp16(int k){
    return (k & ~15) | (((k & 7) >> 1) << 2) | (((k >> 3) & 1) << 1) | (k & 1);
}
DI void barh(int id){ asm volatile("bar.sync %0, %1;" :: "r"(id), "r"(256) : "memory"); }

DI void mma_fp16(float* d, uint32_t a0, uint32_t a1, uint32_t a2, uint32_t a3,
                 uint32_t b0, uint32_t b1){
    asm volatile(
        "mma.sync.aligned.m16n8k16.row.col.f32.f16.f16.f32 "
        "{%0,%1,%2,%3}, {%4,%5,%6,%7}, {%8,%9}, {%0,%1,%2,%3};"
        : "+f"(d[0]), "+f"(d[1]), "+f"(d[2]), "+f"(d[3])
        : "r"(a0), "r"(a1), "r"(a2), "r"(a3), "r"(b0), "r"(b1));
}

// Warp GEMM on pp16-interleaved fp16 buffers. KT = K/16.
template<int KT, int MT, int NT>
DI void wgemm16(const __half* A, int sa, const __half* W, int sw,
                int row0, int ncol0, int lane, float* acc)
{
    const int g = lane >> 2, tg = lane & 3;
#pragma unroll
    for (int i = 0; i < MT*NT*4; i++) acc[i] = 0.f;
#pragma unroll
    for (int kt = 0; kt < KT; kt++){
        const int jo = kt*16 + tg*4;
        uint2 av[2*MT];
#pragma unroll
        for (int mt = 0; mt < MT; mt++){
            av[2*mt]   = *(const uint2*)(A + (row0 + mt*16 + g)*sa + jo);
            av[2*mt+1] = *(const uint2*)(A + (row0 + mt*16 + g + 8)*sa + jo);
        }
#pragma unroll
        for (int nt = 0; nt < NT; nt++){
            uint2 bv = *(const uint2*)(W + (ncol0 + nt*8 + g)*sw + jo);
#pragma unroll
            for (int mt = 0; mt < MT; mt++)
                mma_fp16(acc + (mt*NT+nt)*4,
                         av[2*mt].x, av[2*mt+1].x, av[2*mt].y, av[2*mt+1].y,
                         bv.x, bv.y);
        }
    }
}

// Epilogue: relu(acc+bias) -> fp16, stored pp16-permuted into O (stride so halves)
template<int MT, int NT>
DI void epi_store16(const float* acc, __half* O, int so,
                    int row0, int ncol0, int lane, const float* bias)
{
    const int g = lane >> 2, tg = lane & 3;
#pragma unroll
    for (int mt = 0; mt < MT; mt++){
#pragma unroll
        for (int nt = 0; nt < NT; nt++){
            int c0 = ncol0 + nt*8 + 2*tg;
            int q  = pp16(c0);
            float b0 = bias[c0], b1 = bias[c0+1];
            const float* a = acc + (mt*NT+nt)*4;
            int r = row0 + mt*16 + g;
            *(half2*)(O + r*so + q)     = __floats2half2_rn(fmaxf(a[0]+b0, 0.f), fmaxf(a[1]+b1, 0.f));
            *(half2*)(O + (r+8)*so + q) = __floats2half2_rn(fmaxf(a[2]+b0, 0.f), fmaxf(a[3]+b1, 0.f));
        }
    }
}

DI uint2 pack4h(float4 u, float4 v){
    half2 h0 = __floats2half2_rn(fmaxf(u.x+v.x, 0.f), fmaxf(u.y+v.y, 0.f));
    half2 h1 = __floats2half2_rn(fmaxf(u.z+v.z, 0.f), fmaxf(u.w+v.w, 0.f));
    uint2 o; o.x = *(uint32_t*)&h0; o.y = *(uint32_t*)&h1;
    return o;
}

// ===================== init: prep (weights) + precompute (first layers) fused ==========
// precompute role stages w1 (64x128) + w1pv (46x128) into dynamic smem:
// the FMA chains then run entirely from smem (no LDG latency exposure).
#define INIT_SM ((8192 + 5888) * 4)   // 56320 bytes dynamic

__global__ void init_kernel(const float* __restrict__ x, const float* __restrict__ y,
                            const float* __restrict__ w1,   const float* __restrict__ b1,
                            const float* __restrict__ w1pv, const float* __restrict__ b1pv,
                            const float* __restrict__ w2pp, const float* __restrict__ w3pp,
                            const float* __restrict__ w2pv, const float* __restrict__ w3pv,
                            const float* __restrict__ w1o,  const float* __restrict__ w2o,
                            const float* __restrict__ w3o)
{
    extern __shared__ float dsm[];
    __shared__ float xs[32][65];
    const int tid = threadIdx.x;
    if (blockIdx.x < 128){
        // precompute role
        float* w1s = dsm;            // 64*128
        float* w1ps = dsm + 8192;    // 46*128
        const int b = blockIdx.x;
        for (int i = tid; i < 8192; i += 256) w1s[i] = w1[i];
        for (int i = tid; i < 5888; i += 256) w1ps[i] = w1pv[i];
        for (int idx = tid; idx < 2048; idx += 256){
            int p = idx >> 6, n = idx & 63;
            xs[p][n] = x[(b*32 + p)*64 + n];
        }
        __syncthreads();
        for (int idx = tid; idx < 8192; idx += 256){
            int n = idx >> 7, h = idx & 127;
            float u = b1[h], v = 0.f, upv = b1pv[h];
#pragma unroll
            for (int p = 0; p < 32; p++){
                float xv = xs[p][n];
                u   = fmaf(xv, w1s[p*128 + h], u);
                v   = fmaf(xv, w1s[(32+p)*128 + h], v);
                upv = fmaf(xv, w1ps[p*128 + h], upv);
            }
            int ph = pp16(h);
            g_Upp[(b*64+n)*128 + ph] = u;
            g_Vpp[(b*64+n)*128 + ph] = v;
            g_Upv[(b*64+n)*128 + ph] = upv;
        }
        for (int idx = tid; idx < 1792; idx += 256){
            int v = idx >> 7, h = idx & 127;
            float s = 0.f;
#pragma unroll
            for (int sv = 0; sv < 14; sv++)
                s = fmaf(y[(b*14+sv)*14 + v], w1ps[(32+sv)*128 + h], s);
            g_Vpv[(b*14+v)*128 + pp16(h)] = s;
        }
    } else {
        // prep role: 64 blocks x 256 threads
        const int T = 64*256, t0 = (blockIdx.x - 128)*256 + tid;
        for (int i = t0; i < 128*128; i += T){ int n = i>>7, k = i&127;
            g_W2pp[n*144 + pp16(k)] = __float2half(w2pp[k*128+n]); }
        for (int i = t0; i < 64*128; i += T){ int n = i>>7, k = i&127;
            g_W3pp[n*144 + pp16(k)] = __float2half(w3pp[k*64+n]); }
        for (int i = t0; i < 128*128; i += T){ int n = i>>7, k = i&127;
            g_W2pv[n*144 + pp16(k)] = __float2half(w2pv[k*128+n]); }
        for (int i = t0; i < 64*128; i += T){ int n = i>>7, k = i&127;
            g_W3pv[n*144 + pp16(k)] = __float2half(w3pv[k*64+n]); }
        for (int i = t0; i < 128*160; i += T){ int n = i/160, k = i - n*160;
            g_FO1[n*176 + pp16(k)] = __float2half(w1o[k*128+n]); }
        for (int i = t0; i < 128*128; i += T){ int n = i>>7, k = i&127;
            g_FO2[n*144 + pp16(k)] = __float2half(w2o[k*128+n]); }
        for (int i = t0; i < 64*128; i += T){ int n = i>>7, k = i&127;
            g_FO3[n*144 + pp16(k)] = __float2half(w3o[k*64+n]); }
    }
}

// ===================== fused edge kernel: role-split halves (244 pp / 60 pv) =====================
// per-half smem (bytes, stride 112128):
//   W2[128x144h]=36864 | W3[64x144h]=18432 | H1a | H1b | H2 (18432 each) | b2(512) | b3(256) | part(512)
#define EH_STRIDE 112128
#define EH_W2   0
#define EH_W3   36864
#define EH_H1A  55296
#define EH_H1B  73728
#define EH_H2   92160
#define EH_B2   110592
#define EH_B3   111104
#define EH_PT   111360
#define EDGE_SM (2*EH_STRIDE)      // 224256

#define N_PP_HALVES 244
#define N_HALVES    304

DI void pp_loop(char* hb, int htid, int lane, int barid, int tstart, int tend)
{
    __half* W2   = (__half*)(hb + EH_W2);
    __half* W3   = (__half*)(hb + EH_W3);
    __half* H1a  = (__half*)(hb + EH_H1A);
    __half* H1b  = (__half*)(hb + EH_H1B);
    __half* H2   = (__half*)(hb + EH_H2);
    float* bias2 = (float*)(hb + EH_B2);
    float* bias3 = (float*)(hb + EH_B3);
    float* part  = (float*)(hb + EH_PT);
    const int hw = htid >> 5;
    const int g = lane >> 2, tg = lane & 3;
    const int rg = hw & 1, cg = hw >> 1;
    const int c4 = htid & 31;
    const int r0 = htid >> 5;

    __half* Hc = H1a;
    __half* Hn = H1b;

    {   // prologue build
        const int b = tstart >> 6, r = tstart & 63;
        const float* Ur = g_Upp + ((size_t)b*64 + r)*128;
        const float* Vb = g_Vpp + (size_t)b*64*128;
        float4 u = *(const float4*)(Ur + c4*4);
#pragma unroll
        for (int it = 0; it < 8; it++){
            int s = r0 + it*8;
            float4 v = *(const float4*)(Vb + s*128 + c4*4);
            *(uint2*)(Hc + s*144 + c4*4) = pack4h(u, v);
        }
    }
    barh(barid);

    for (int t = tstart; t < tend; t++){
        {
            float acc[32];
            wgemm16<8,2,4>(Hc, 144, W2, 144, rg*32, cg*32, lane, acc);
            epi_store16<2,4>(acc, H2, 144, rg*32, cg*32, lane, bias2);
        }
        barh(barid);

        const bool have_next = (t + 1 < tend);
        float4 u_n; float4 v_n[8];
        if (have_next){
            const int bn = (t+1) >> 6, rn = (t+1) & 63;
            const float* Ur = g_Upp + ((size_t)bn*64 + rn)*128;
            const float* Vb = g_Vpp + (size_t)bn*64*128;
            u_n = *(const float4*)(Ur + c4*4);
#pragma unroll
            for (int it = 0; it < 8; it++)
                v_n[it] = *(const float4*)(Vb + (r0 + it*8)*128 + c4*4);
        }

        float acc3[16];
        wgemm16<8,2,2>(H2, 144, W3, 144, rg*32, cg*16, lane, acc3);

        if (have_next){
#pragma unroll
            for (int it = 0; it < 8; it++)
                *(uint2*)(Hn + (r0 + it*8)*144 + c4*4) = pack4h(u_n, v_n[it]);
        }

        {   // self-excluded column reduce -> part
            const int r = t & 63;
#pragma unroll
            for (int nt = 0; nt < 2; nt++){
                int c = cg*16 + nt*8 + tg*2;
                float b0 = bias3[c], b1 = bias3[c+1];
                float t0 = 0.f, t1 = 0.f;
#pragma unroll
                for (int mt = 0; mt < 2; mt++){
                    int ra = rg*32 + mt*16 + g, rb = ra + 8;
                    bool z1 = (ra == r), z2 = (rb == r);
                    const float* a = acc3 + (mt*2+nt)*4;
                    t0 += (z1 ? 0.f : fmaxf(a[0]+b0, 0.f)) + (z2 ? 0.f : fmaxf(a[2]+b0, 0.f));
                    t1 += (z1 ? 0.f : fmaxf(a[1]+b1, 0.f)) + (z2 ? 0.f : fmaxf(a[3]+b1, 0.f));
                }
#pragma unroll
                for (int m = 4; m < 32; m <<= 1){
                    t0 += __shfl_xor_sync(0xffffffffu, t0, m);
                    t1 += __shfl_xor_sync(0xffffffffu, t1, m);
                }
                if (g == 0){ part[rg*64 + c] = t0; part[rg*64 + c + 1] = t1; }
            }
        }
        barh(barid);
        if (htid < 64){
            const int b = t >> 6, r = t & 63;
            g_EppT[((size_t)b*64 + htid)*64 + r] = part[htid] + part[64 + htid];
        }
        __half* tmp = Hc; Hc = Hn; Hn = tmp;
    }
}

DI void pv_loop(char* hb, int htid, int lane, int barid, int tstart, int tend)
{
    __half* W2   = (__half*)(hb + EH_W2);
    __half* W3   = (__half*)(hb + EH_W3);
    __half* H1a  = (__half*)(hb + EH_H1A);
    __half* H1b  = (__half*)(hb + EH_H1B);
    __half* H2   = (__half*)(hb + EH_H2);
    float* bias2 = (float*)(hb + EH_B2);
    float* bias3 = (float*)(hb + EH_B3);
    const int hw = htid >> 5;
    const int g = lane >> 2, tg = lane & 3;
    const int rg = hw & 1, cg = hw >> 1;
    const int c4 = htid & 31;
    const int r0 = htid >> 5;

    __half* Hc = H1a;
    __half* Hn = H1b;

    {   // prologue build: 4 receivers x 16 slots (vv>=14 pad)
        const int b = tstart >> 4, grp = tstart & 15;
        const float* Ub = g_Upv + ((size_t)b*64 + grp*4)*128;
        const float* Vb = g_Vpv + (size_t)b*14*128;
#pragma unroll
        for (int it = 0; it < 8; it++){
            int row = r0 + it*8;
            int ri = row >> 4, vv = row & 15;
            uint2 o; o.x = 0u; o.y = 0u;
            if (vv < 14)
                o = pack4h(*(const float4*)(Ub + ri*128 + c4*4),
                           *(const float4*)(Vb + vv*128 + c4*4));
            *(uint2*)(Hc + row*144 + c4*4) = o;
        }
    }
    barh(barid);

    for (int t = tstart; t < tend; t++){
        {
            float acc[32];
            wgemm16<8,2,4>(Hc, 144, W2, 144, rg*32, cg*32, lane, acc);
            epi_store16<2,4>(acc, H2, 144, rg*32, cg*32, lane, bias2);
        }
        barh(barid);

        const bool have_next = (t + 1 < tend);
        float4 u_n[8]; float4 v_n[8]; bool valid[8];
        if (have_next){
            const int bn = (t+1) >> 4, gn = (t+1) & 15;
            const float* Ub = g_Upv + ((size_t)bn*64 + gn*4)*128;
            const float* Vb = g_Vpv + (size_t)bn*14*128;
#pragma unroll
            for (int it = 0; it < 8; it++){
                int row = r0 + it*8;
                int ri = row >> 4, vv = row & 15;
                valid[it] = (vv < 14);
                if (valid[it]){
                    u_n[it] = *(const float4*)(Ub + ri*128 + c4*4);
                    v_n[it] = *(const float4*)(Vb + vv*128 + c4*4);
                }
            }
        }

        float acc3[16];
        wgemm16<8,2,2>(H2, 144, W3, 144, rg*32, cg*16, lane, acc3);

        if (have_next){
#pragma unroll
            for (int it = 0; it < 8; it++){
                int row = r0 + it*8;
                uint2 o; o.x = 0u; o.y = 0u;
                if (valid[it]) o = pack4h(u_n[it], v_n[it]);
                *(uint2*)(Hn + row*144 + c4*4) = o;
            }
        }

        {   // per-receiver reduce -> gmem (receiver = grp*4 + rg*2 + mt)
            const int b = t >> 4, grp = t & 15;
            bool z2 = (g >= 6);
#pragma unroll
            for (int mt = 0; mt < 2; mt++){
                int recv = grp*4 + rg*2 + mt;
#pragma unroll
                for (int nt = 0; nt < 2; nt++){
                    int c = cg*16 + nt*8 + tg*2;
                    float b0 = bias3[c], b1 = bias3[c+1];
                    const float* a = acc3 + (mt*2+nt)*4;
                    float t0 = fmaxf(a[0]+b0, 0.f) + (z2 ? 0.f : fmaxf(a[2]+b0, 0.f));
                    float t1 = fmaxf(a[1]+b1, 0.f) + (z2 ? 0.f : fmaxf(a[3]+b1, 0.f));
#pragma unroll
                    for (int m = 4; m < 32; m <<= 1){
                        t0 += __shfl_xor_sync(0xffffffffu, t0, m);
                        t1 += __shfl_xor_sync(0xffffffffu, t1, m);
                    }
                    if (g == 0){
                        g_EpvT[((size_t)b*64 + c)*64 + recv]     = t0;
                        g_EpvT[((size_t)b*64 + c + 1)*64 + recv] = t1;
                    }
                }
            }
        }
        barh(barid);
        __half* tmp = Hc; Hc = Hn; Hn = tmp;
    }
}

__global__ __launch_bounds__(512, 1) void edge_kernel(const float* __restrict__ b2pp,
                                                      const float* __restrict__ b3pp,
                                                      const float* __restrict__ b2pv,
                                                      const float* __restrict__ b3pv)
{
    extern __shared__ char sm[];
    const int tid = threadIdx.x;
    const int half_ = tid >> 8, htid = tid & 255;
    const int lane = tid & 31;
    const int hidx = blockIdx.x*2 + half_;
    const bool is_pp = (hidx < N_PP_HALVES);
    char* hb = sm + half_*EH_STRIDE;
    const int barid = 1 + half_;

    {
        const float4* src2 = (const float4*)(is_pp ? (const void*)g_W2pp : (const void*)g_W2pv);
        const float4* src3 = (const float4*)(is_pp ? (const void*)g_W3pp : (const void*)g_W3pv);
        float4* d2 = (float4*)(hb + EH_W2);
        float4* d3 = (float4*)(hb + EH_W3);
        for (int i = htid; i < 2304; i += 256) d2[i] = src2[i];
        for (int i = htid; i < 1152; i += 256) d3[i] = src3[i];
        float* bias2 = (float*)(hb + EH_B2);
        float* bias3 = (float*)(hb + EH_B3);
        if (htid < 128) bias2[htid] = is_pp ? b2pp[htid] : b2pv[htid];
        if (htid < 64)  bias3[htid] = is_pp ? b3pp[htid] : b3pv[htid];
    }
    __syncthreads();

    if (is_pp){
        const int idx = hidx;
        const int tstart = (int)((long long)8192*idx/N_PP_HALVES);
        const int tend   = (int)((long long)8192*(idx+1)/N_PP_HALVES);
        pp_loop(hb, htid, lane, barid, tstart, tend);
    } else {
        const int idx = hidx - N_PP_HALVES;
        const int npv = N_HALVES - N_PP_HALVES;
        const int tstart = (int)((long long)2048*idx/npv);
        const int tend   = (int)((long long)2048*(idx+1)/npv);
        pv_loop(hb, htid, lane, barid, tstart, tend);
    }
}

// ===================== object MLP + pool + classifier: 1 graph/block, fp16 =====================
#define OB_C   0
#define OB_W   22528
#define OB_H2  67584
#define OB_B1  86016
#define OB_B2  86528
#define OB_B3  87040
#define OB_FCB 87296
#define OB_PT  87328
#define OB_PL  87840
#define OB_SM  88096

__global__ __launch_bounds__(256) void obj_kernel(const float* __restrict__ x,
                                                  const float* __restrict__ b1v,
                                                  const float* __restrict__ b2v,
                                                  const float* __restrict__ b3v,
                                                  const float* __restrict__ fcw,
                                                  const float* __restrict__ fcb,
                                                  float* __restrict__ out)
{
    extern __shared__ char sm[];
    __half* C    = (__half*)(sm + OB_C);
    __half* Wbuf = (__half*)(sm + OB_W);
    __half* H2   = (__half*)(sm + OB_H2);
    __half* H3   = (__half*)(sm + OB_C);          // overlays C, stride 176
    float* bias1  = (float*)(sm + OB_B1);
    float* bias2  = (float*)(sm + OB_B2);
    float* bias3  = (float*)(sm + OB_B3);
    float* fcbs   = (float*)(sm + OB_FCB);
    float* part   = (float*)(sm + OB_PT);
    float* pooled = (float*)(sm + OB_PL);
    const int tid = threadIdx.x, wid = tid >> 5, lane = tid & 31;
    const int g = lane >> 2, tg = lane & 3;
    const int rg = wid & 1, cg = wid >> 1;
    const int bg = blockIdx.x;

    for (int i = tid; i < 2816; i += 256) ((float4*)Wbuf)[i] = ((const float4*)g_FO1)[i];
    if (tid < 128) bias1[tid] = b1v[tid];
    if (tid < 128) bias2[tid] = b2v[tid];
    if (tid < 64)  bias3[tid] = b3v[tid];
    if (tid < 5)   fcbs[tid]  = fcb[tid];
    for (int i = tid; i < 160*64; i += 256){
        int k = i >> 6, n = i & 63;
        float v;
        if (k < 32)      v = x[(bg*32 + k)*64 + n];
        else if (k < 96) v = g_EppT[((size_t)bg*64 + (k-32))*64 + n];
        else             v = g_EpvT[((size_t)bg*64 + (k-96))*64 + n];
        C[n*176 + pp16(k)] = __float2half(v);
    }
    __syncthreads();
    {
        float acc[32];
        wgemm16<10,2,4>(C, 176, Wbuf, 176, rg*32, cg*32, lane, acc);
        epi_store16<2,4>(acc, H2, 144, rg*32, cg*32, lane, bias1);
    }
    __syncthreads();
    for (int i = tid; i < 2304; i += 256) ((float4*)Wbuf)[i] = ((const float4*)g_FO2)[i];
    __syncthreads();
    {
        float acc[32];
        wgemm16<8,2,4>(H2, 144, Wbuf, 144, rg*32, cg*32, lane, acc);
        __syncthreads();
        epi_store16<2,4>(acc, H3, 176, rg*32, cg*32, lane, bias2);
    }
    __syncthreads();
    for (int i = tid; i < 1152; i += 256) ((float4*)Wbuf)[i] = ((const float4*)g_FO3)[i];
    __syncthreads();
    {
        float acc[16];
        wgemm16<8,2,2>(H3, 176, Wbuf, 144, rg*32, cg*16, lane, acc);
#pragma unroll
        for (int nt = 0; nt < 2; nt++){
            int c = cg*16 + nt*8 + tg*2;
            float b0 = bias3[c], b1 = bias3[c+1];
            float t0 = 0.f, t1 = 0.f;
#pragma unroll
            for (int mt = 0; mt < 2; mt++){
                const float* a = acc + (mt*2+nt)*4;
                t0 += fmaxf(a[0]+b0, 0.f) + fmaxf(a[2]+b0, 0.f);
                t1 += fmaxf(a[1]+b1, 0.f) + fmaxf(a[3]+b1, 0.f);
            }
#pragma unroll
            for (int m = 4; m < 32; m <<= 1){
                t0 += __shfl_xor_sync(0xffffffffu, t0, m);
                t1 += __shfl_xor_sync(0xffffffffu, t1, m);
            }
            if (g == 0){ part[rg*64 + c] = t0; part[rg*64 + c + 1] = t1; }
        }
    }
    __syncthreads();
    if (tid < 64) pooled[tid] = part[tid] + part[64 + tid];
    __syncthreads();
    if (tid < 5){
        float s = fcbs[tid];
#pragma unroll 8
        for (int j = 0; j < 64; j++)
            s = fmaf(pooled[j], fcw[j*5 + tid], s);
        out[bg*5 + tid] = s;
    }
}

// ===================== launch =====================
extern "C" void kernel_launch(void* const* d_in, const int* in_sizes, int n_in,
                              void* d_out, int out_size)
{
    const float* x       = (const float*)d_in[0];
    const float* y       = (const float*)d_in[1];
    const float* fr1_w   = (const float*)d_in[2];
    const float* fr1_b   = (const float*)d_in[3];
    const float* fr2_w   = (const float*)d_in[4];
    const float* fr2_b   = (const float*)d_in[5];
    const float* fr3_w   = (const float*)d_in[6];
    const float* fr3_b   = (const float*)d_in[7];
    const float* fr1pv_w = (const float*)d_in[8];
    const float* fr1pv_b = (const float*)d_in[9];
    const float* fr2pv_w = (const float*)d_in[10];
    const float* fr2pv_b = (const float*)d_in[11];
    const float* fr3pv_w = (const float*)d_in[12];
    const float* fr3pv_b = (const float*)d_in[13];
    const float* fo1_w   = (const float*)d_in[14];
    const float* fo1_b   = (const float*)d_in[15];
    const float* fo2_w   = (const float*)d_in[16];
    const float* fo2_b   = (const float*)d_in[17];
    const float* fo3_w   = (const float*)d_in[18];
    const float* fo3_b   = (const float*)d_in[19];
    const float* fc_w    = (const float*)d_in[20];
    const float* fc_b    = (const float*)d_in[21];
    float* out = (float*)d_out;

    cudaFuncSetAttribute(init_kernel, cudaFuncAttributeMaxDynamicSharedMemorySize, INIT_SM);
    cudaFuncSetAttribute(edge_kernel, cudaFuncAttributeMaxDynamicSharedMemorySize, EDGE_SM);
    cudaFuncSetAttribute(obj_kernel,  cudaFuncAttributeMaxDynamicSharedMemorySize, OB_SM);

    init_kernel<<<192, 256, INIT_SM>>>(x, y, fr1_w, fr1_b, fr1pv_w, fr1pv_b,
                                       fr2_w, fr3_w, fr2pv_w, fr3pv_w, fo1_w, fo2_w, fo3_w);
    edge_kernel<<<152, 512, EDGE_SM>>>(fr2_b, fr3_b, fr2pv_b, fr3pv_b);
    obj_kernel<<<128, 256, OB_SM>>>(x, fo1_b, fo2_b, fo3_b, fc_w, fc_b, out);
}

// round 15
// speedup vs baseline: 1.0182x; 1.0182x over previous
#include <cuda_runtime.h>
#include <cuda_fp16.h>
#include <stdint.h>

#define DI __device__ __forceinline__

// ===================== device scratch (no allocations) =====================
__device__ float g_Upp[128*64*128];
__device__ float g_Vpp[128*64*128];
__device__ float g_Upv[128*64*128];
__device__ float g_Vpv[128*14*128];
__device__ float g_EppT[128*64*64];   // transposed: [b][c][r]
__device__ float g_EpvT[128*64*64];   // transposed: [b][c][r]

// pre-transposed fp16 weight images, pp16-permuted k, stride 144 halves (176 for FO1)
__device__ __align__(16) __half g_W2pp[128*144];
__device__ __align__(16) __half g_W3pp[64*144];
__device__ __align__(16) __half g_W2pv[128*144];
__device__ __align__(16) __half g_W3pv[64*144];
__device__ __align__(16) __half g_FO1 [128*176];
__device__ __align__(16) __half g_FO2 [128*144];
__device__ __align__(16) __half g_FO3 [64*144];

// ===================== helpers =====================
DI int pp16(int k){
    return (k & ~15) | (((k & 7) >> 1) << 2) | (((k >> 3) & 1) << 1) | (k & 1);
}
DI void barh(int id){ asm volatile("bar.sync %0, %1;" :: "r"(id), "r"(256) : "memory"); }

DI void mma_fp16(float* d, uint32_t a0, uint32_t a1, uint32_t a2, uint32_t a3,
                 uint32_t b0, uint32_t b1){
    asm volatile(
        "mma.sync.aligned.m16n8k16.row.col.f32.f16.f16.f32 "
        "{%0,%1,%2,%3}, {%4,%5,%6,%7}, {%8,%9}, {%0,%1,%2,%3};"
        : "+f"(d[0]), "+f"(d[1]), "+f"(d[2]), "+f"(d[3])
        : "r"(a0), "r"(a1), "r"(a2), "r"(a3), "r"(b0), "r"(b1));
}

// Warp GEMM on pp16-interleaved fp16 buffers. KT = K/16.
template<int KT, int MT, int NT>
DI void wgemm16(const __half* A, int sa, const __half* W, int sw,
                int row0, int ncol0, int lane, float* acc)
{
    const int g = lane >> 2, tg = lane & 3;
#pragma unroll
    for (int i = 0; i < MT*NT*4; i++) acc[i] = 0.f;
#pragma unroll
    for (int kt = 0; kt < KT; kt++){
        const int jo = kt*16 + tg*4;
        uint2 av[2*MT];
#pragma unroll
        for (int mt = 0; mt < MT; mt++){
            av[2*mt]   = *(const uint2*)(A + (row0 + mt*16 + g)*sa + jo);
            av[2*mt+1] = *(const uint2*)(A + (row0 + mt*16 + g + 8)*sa + jo);
        }
#pragma unroll
        for (int nt = 0; nt < NT; nt++){
            uint2 bv = *(const uint2*)(W + (ncol0 + nt*8 + g)*sw + jo);
#pragma unroll
            for (int mt = 0; mt < MT; mt++)
                mma_fp16(acc + (mt*NT+nt)*4,
                         av[2*mt].x, av[2*mt+1].x, av[2*mt].y, av[2*mt+1].y,
                         bv.x, bv.y);
        }
    }
}

// Epilogue: relu(acc+bias) -> fp16, stored pp16-permuted into O (stride so halves)
template<int MT, int NT>
DI void epi_store16(const float* acc, __half* O, int so,
                    int row0, int ncol0, int lane, const float* bias)
{
    const int g = lane >> 2, tg = lane & 3;
#pragma unroll
    for (int mt = 0; mt < MT; mt++){
#pragma unroll
        for (int nt = 0; nt < NT; nt++){
            int c0 = ncol0 + nt*8 + 2*tg;
            int q  = pp16(c0);
            float b0 = bias[c0], b1 = bias[c0+1];
            const float* a = acc + (mt*NT+nt)*4;
            int r = row0 + mt*16 + g;
            *(half2*)(O + r*so + q)     = __floats2half2_rn(fmaxf(a[0]+b0, 0.f), fmaxf(a[1]+b1, 0.f));
            *(half2*)(O + (r+8)*so + q) = __floats2half2_rn(fmaxf(a[2]+b0, 0.f), fmaxf(a[3]+b1, 0.f));
        }
    }
}

DI uint2 pack4h(float4 u, float4 v){
    half2 h0 = __floats2half2_rn(fmaxf(u.x+v.x, 0.f), fmaxf(u.y+v.y, 0.f));
    half2 h1 = __floats2half2_rn(fmaxf(u.z+v.z, 0.f), fmaxf(u.w+v.w, 0.f));
    uint2 o; o.x = *(uint32_t*)&h0; o.y = *(uint32_t*)&h1;
    return o;
}

// ===================== init: precompute (256 blocks) + prep (48 blocks) =====================
// precompute: weight-register-reuse form. Thread: fixed h, 16 n's in registers.
__global__ __launch_bounds__(256) void init_kernel(
    const float* __restrict__ x, const float* __restrict__ y,
    const float* __restrict__ w1,   const float* __restrict__ b1,
    const float* __restrict__ w1pv, const float* __restrict__ b1pv,
    const float* __restrict__ w2pp, const float* __restrict__ w3pp,
    const float* __restrict__ w2pv, const float* __restrict__ w3pv,
    const float* __restrict__ w1o,  const float* __restrict__ w2o,
    const float* __restrict__ w3o)
{
    const int tid = threadIdx.x;
    if (blockIdx.x < 256){
        // precompute role: block handles (b, nsel) — 32 particles
        __shared__ float xs[32][33];
        const int b = blockIdx.x >> 1, nsel = blockIdx.x & 1, n0 = nsel*32;
        const int h = tid & 127, which = tid >> 7;    // 2 threads per h, 16 n's each
        for (int i = tid; i < 1024; i += 256){
            int p = i >> 5, n = i & 31;
            xs[p][n] = x[(b*32 + p)*64 + n0 + n];
        }
        __syncthreads();
        float u[16], v[16], upv[16];
        const float bu = b1[h], bup = b1pv[h];
#pragma unroll
        for (int i = 0; i < 16; i++){ u[i] = bu; v[i] = 0.f; upv[i] = bup; }
        const int nb = which*16;
#pragma unroll 4
        for (int p = 0; p < 32; p++){
            float wa = w1[p*128 + h];
            float wb = w1[(32+p)*128 + h];
            float wc = w1pv[p*128 + h];
#pragma unroll
            for (int i = 0; i < 16; i++){
                float xv = xs[p][nb + i];
                u[i]   = fmaf(xv, wa, u[i]);
                v[i]   = fmaf(xv, wb, v[i]);
                upv[i] = fmaf(xv, wc, upv[i]);
            }
        }
        const int ph = pp16(h);
#pragma unroll
        for (int i = 0; i < 16; i++){
            int n = n0 + nb + i;
            g_Upp[((size_t)b*64 + n)*128 + ph] = u[i];
            g_Vpp[((size_t)b*64 + n)*128 + ph] = v[i];
            g_Upv[((size_t)b*64 + n)*128 + ph] = upv[i];
        }
        if (nsel == 0){
            float s[7];
#pragma unroll
            for (int j = 0; j < 7; j++) s[j] = 0.f;
#pragma unroll
            for (int sv = 0; sv < 14; sv++){
                float w = w1pv[(32+sv)*128 + h];
#pragma unroll
                for (int j = 0; j < 7; j++)
                    s[j] = fmaf(y[(b*14 + sv)*14 + which*7 + j], w, s[j]);
            }
#pragma unroll
            for (int j = 0; j < 7; j++)
                g_Vpv[((size_t)b*14 + which*7 + j)*128 + ph] = s[j];
        }
    } else {
        // prep role: 48 blocks x 256 threads
        const int T = 48*256, t0 = (blockIdx.x - 256)*256 + tid;
        for (int i = t0; i < 128*128; i += T){ int n = i>>7, k = i&127;
            g_W2pp[n*144 + pp16(k)] = __float2half(w2pp[k*128+n]); }
        for (int i = t0; i < 64*128; i += T){ int n = i>>7, k = i&127;
            g_W3pp[n*144 + pp16(k)] = __float2half(w3pp[k*64+n]); }
        for (int i = t0; i < 128*128; i += T){ int n = i>>7, k = i&127;
            g_W2pv[n*144 + pp16(k)] = __float2half(w2pv[k*128+n]); }
        for (int i = t0; i < 64*128; i += T){ int n = i>>7, k = i&127;
            g_W3pv[n*144 + pp16(k)] = __float2half(w3pv[k*64+n]); }
        for (int i = t0; i < 128*160; i += T){ int n = i/160, k = i - n*160;
            g_FO1[n*176 + pp16(k)] = __float2half(w1o[k*128+n]); }
        for (int i = t0; i < 128*128; i += T){ int n = i>>7, k = i&127;
            g_FO2[n*144 + pp16(k)] = __float2half(w2o[k*128+n]); }
        for (int i = t0; i < 64*128; i += T){ int n = i>>7, k = i&127;
            g_FO3[n*144 + pp16(k)] = __float2half(w3o[k*64+n]); }
    }
}

// ===================== fused edge kernel: role-split halves (244 pp / 60 pv) =====================
// per-half smem (bytes, stride 112128):
//   W2[128x144h]=36864 | W3[64x144h]=18432 | H1a | H1b | H2 (18432 each) | b2(512) | b3(256) | part(512)
#define EH_STRIDE 112128
#define EH_W2   0
#define EH_W3   36864
#define EH_H1A  55296
#define EH_H1B  73728
#define EH_H2   92160
#define EH_B2   110592
#define EH_B3   111104
#define EH_PT   111360
#define EDGE_SM (2*EH_STRIDE)      // 224256

#define N_PP_HALVES 244
#define N_HALVES    304

DI void pp_loop(char* hb, int htid, int lane, int barid, int tstart, int tend)
{
    __half* W2   = (__half*)(hb + EH_W2);
    __half* W3   = (__half*)(hb + EH_W3);
    __half* H1a  = (__half*)(hb + EH_H1A);
    __half* H1b  = (__half*)(hb + EH_H1B);
    __half* H2   = (__half*)(hb + EH_H2);
    float* bias2 = (float*)(hb + EH_B2);
    float* bias3 = (float*)(hb + EH_B3);
    float* part  = (float*)(hb + EH_PT);
    const int hw = htid >> 5;
    const int g = lane >> 2, tg = lane & 3;
    const int rg = hw & 1, cg = hw >> 1;
    const int c4 = htid & 31;
    const int r0 = htid >> 5;

    __half* Hc = H1a;
    __half* Hn = H1b;

    {   // prologue build
        const int b = tstart >> 6, r = tstart & 63;
        const float* Ur = g_Upp + ((size_t)b*64 + r)*128;
        const float* Vb = g_Vpp + (size_t)b*64*128;
        float4 u = *(const float4*)(Ur + c4*4);
#pragma unroll
        for (int it = 0; it < 8; it++){
            int s = r0 + it*8;
            float4 v = *(const float4*)(Vb + s*128 + c4*4);
            *(uint2*)(Hc + s*144 + c4*4) = pack4h(u, v);
        }
    }
    barh(barid);

    for (int t = tstart; t < tend; t++){
        {
            float acc[32];
            wgemm16<8,2,4>(Hc, 144, W2, 144, rg*32, cg*32, lane, acc);
            epi_store16<2,4>(acc, H2, 144, rg*32, cg*32, lane, bias2);
        }
        barh(barid);

        const bool have_next = (t + 1 < tend);
        float4 u_n; float4 v_n[8];
        if (have_next){
            const int bn = (t+1) >> 6, rn = (t+1) & 63;
            const float* Ur = g_Upp + ((size_t)bn*64 + rn)*128;
            const float* Vb = g_Vpp + (size_t)bn*64*128;
            u_n = *(const float4*)(Ur + c4*4);
#pragma unroll
            for (int it = 0; it < 8; it++)
                v_n[it] = *(const float4*)(Vb + (r0 + it*8)*128 + c4*4);
        }

        float acc3[16];
        wgemm16<8,2,2>(H2, 144, W3, 144, rg*32, cg*16, lane, acc3);

        if (have_next){
#pragma unroll
            for (int it = 0; it < 8; it++)
                *(uint2*)(Hn + (r0 + it*8)*144 + c4*4) = pack4h(u_n, v_n[it]);
        }

        {   // self-excluded column reduce -> part
            const int r = t & 63;
#pragma unroll
            for (int nt = 0; nt < 2; nt++){
                int c = cg*16 + nt*8 + tg*2;
                float b0 = bias3[c], b1 = bias3[c+1];
                float t0 = 0.f, t1 = 0.f;
#pragma unroll
                for (int mt = 0; mt < 2; mt++){
                    int ra = rg*32 + mt*16 + g, rb = ra + 8;
                    bool z1 = (ra == r), z2 = (rb == r);
                    const float* a = acc3 + (mt*2+nt)*4;
                    t0 += (z1 ? 0.f : fmaxf(a[0]+b0, 0.f)) + (z2 ? 0.f : fmaxf(a[2]+b0, 0.f));
                    t1 += (z1 ? 0.f : fmaxf(a[1]+b1, 0.f)) + (z2 ? 0.f : fmaxf(a[3]+b1, 0.f));
                }
#pragma unroll
                for (int m = 4; m < 32; m <<= 1){
                    t0 += __shfl_xor_sync(0xffffffffu, t0, m);
                    t1 += __shfl_xor_sync(0xffffffffu, t1, m);
                }
                if (g == 0){ part[rg*64 + c] = t0; part[rg*64 + c + 1] = t1; }
            }
        }
        barh(barid);
        if (htid < 64){
            const int b = t >> 6, r = t & 63;
            g_EppT[((size_t)b*64 + htid)*64 + r] = part[htid] + part[64 + htid];
        }
        __half* tmp = Hc; Hc = Hn; Hn = tmp;
    }
}

DI void pv_loop(char* hb, int htid, int lane, int barid, int tstart, int tend)
{
    __half* W2   = (__half*)(hb + EH_W2);
    __half* W3   = (__half*)(hb + EH_W3);
    __half* H1a  = (__half*)(hb + EH_H1A);
    __half* H1b  = (__half*)(hb + EH_H1B);
    __half* H2   = (__half*)(hb + EH_H2);
    float* bias2 = (float*)(hb + EH_B2);
    float* bias3 = (float*)(hb + EH_B3);
    const int hw = htid >> 5;
    const int g = lane >> 2, tg = lane & 3;
    const int rg = hw & 1, cg = hw >> 1;
    const int c4 = htid & 31;
    const int r0 = htid >> 5;

    __half* Hc = H1a;
    __half* Hn = H1b;

    {   // prologue build: 4 receivers x 16 slots (vv>=14 pad)
        const int b = tstart >> 4, grp = tstart & 15;
        const float* Ub = g_Upv + ((size_t)b*64 + grp*4)*128;
        const float* Vb = g_Vpv + (size_t)b*14*128;
#pragma unroll
        for (int it = 0; it < 8; it++){
            int row = r0 + it*8;
            int ri = row >> 4, vv = row & 15;
            uint2 o; o.x = 0u; o.y = 0u;
            if (vv < 14)
                o = pack4h(*(const float4*)(Ub + ri*128 + c4*4),
                           *(const float4*)(Vb + vv*128 + c4*4));
            *(uint2*)(Hc + row*144 + c4*4) = o;
        }
    }
    barh(barid);

    for (int t = tstart; t < tend; t++){
        {
            float acc[32];
            wgemm16<8,2,4>(Hc, 144, W2, 144, rg*32, cg*32, lane, acc);
            epi_store16<2,4>(acc, H2, 144, rg*32, cg*32, lane, bias2);
        }
        barh(barid);

        const bool have_next = (t + 1 < tend);
        float4 u_n[8]; float4 v_n[8]; bool valid[8];
        if (have_next){
            const int bn = (t+1) >> 4, gn = (t+1) & 15;
            const float* Ub = g_Upv + ((size_t)bn*64 + gn*4)*128;
            const float* Vb = g_Vpv + (size_t)bn*14*128;
#pragma unroll
            for (int it = 0; it < 8; it++){
                int row = r0 + it*8;
                int ri = row >> 4, vv = row & 15;
                valid[it] = (vv < 14);
                if (valid[it]){
                    u_n[it] = *(const float4*)(Ub + ri*128 + c4*4);
                    v_n[it] = *(const float4*)(Vb + vv*128 + c4*4);
                }
            }
        }

        float acc3[16];
        wgemm16<8,2,2>(H2, 144, W3, 144, rg*32, cg*16, lane, acc3);

        if (have_next){
#pragma unroll
            for (int it = 0; it < 8; it++){
                int row = r0 + it*8;
                uint2 o; o.x = 0u; o.y = 0u;
                if (valid[it]) o = pack4h(u_n[it], v_n[it]);
                *(uint2*)(Hn + row*144 + c4*4) = o;
            }
        }

        {   // per-receiver reduce -> gmem (receiver = grp*4 + rg*2 + mt)
            const int b = t >> 4, grp = t & 15;
            bool z2 = (g >= 6);
#pragma unroll
            for (int mt = 0; mt < 2; mt++){
                int recv = grp*4 + rg*2 + mt;
#pragma unroll
                for (int nt = 0; nt < 2; nt++){
                    int c = cg*16 + nt*8 + tg*2;
                    float b0 = bias3[c], b1 = bias3[c+1];
                    const float* a = acc3 + (mt*2+nt)*4;
                    float t0 = fmaxf(a[0]+b0, 0.f) + (z2 ? 0.f : fmaxf(a[2]+b0, 0.f));
                    float t1 = fmaxf(a[1]+b1, 0.f) + (z2 ? 0.f : fmaxf(a[3]+b1, 0.f));
#pragma unroll
                    for (int m = 4; m < 32; m <<= 1){
                        t0 += __shfl_xor_sync(0xffffffffu, t0, m);
                        t1 += __shfl_xor_sync(0xffffffffu, t1, m);
                    }
                    if (g == 0){
                        g_EpvT[((size_t)b*64 + c)*64 + recv]     = t0;
                        g_EpvT[((size_t)b*64 + c + 1)*64 + recv] = t1;
                    }
                }
            }
        }
        barh(barid);
        __half* tmp = Hc; Hc = Hn; Hn = tmp;
    }
}

__global__ __launch_bounds__(512, 1) void edge_kernel(const float* __restrict__ b2pp,
                                                      const float* __restrict__ b3pp,
                                                      const float* __restrict__ b2pv,
                                                      const float* __restrict__ b3pv)
{
    extern __shared__ char sm[];
    const int tid = threadIdx.x;
    const int half_ = tid >> 8, htid = tid & 255;
    const int lane = tid & 31;
    const int hidx = blockIdx.x*2 + half_;
    const bool is_pp = (hidx < N_PP_HALVES);
    char* hb = sm + half_*EH_STRIDE;
    const int barid = 1 + half_;

    {
        const float4* src2 = (const float4*)(is_pp ? (const void*)g_W2pp : (const void*)g_W2pv);
        const float4* src3 = (const float4*)(is_pp ? (const void*)g_W3pp : (const void*)g_W3pv);
        float4* d2 = (float4*)(hb + EH_W2);
        float4* d3 = (float4*)(hb + EH_W3);
        for (int i = htid; i < 2304; i += 256) d2[i] = src2[i];
        for (int i = htid; i < 1152; i += 256) d3[i] = src3[i];
        float* bias2 = (float*)(hb + EH_B2);
        float* bias3 = (float*)(hb + EH_B3);
        if (htid < 128) bias2[htid] = is_pp ? b2pp[htid] : b2pv[htid];
        if (htid < 64)  bias3[htid] = is_pp ? b3pp[htid] : b3pv[htid];
    }
    __syncthreads();

    if (is_pp){
        const int idx = hidx;
        const int tstart = (int)((long long)8192*idx/N_PP_HALVES);
        const int tend   = (int)((long long)8192*(idx+1)/N_PP_HALVES);
        pp_loop(hb, htid, lane, barid, tstart, tend);
    } else {
        const int idx = hidx - N_PP_HALVES;
        const int npv = N_HALVES - N_PP_HALVES;
        const int tstart = (int)((long long)2048*idx/npv);
        const int tend   = (int)((long long)2048*(idx+1)/npv);
        pv_loop(hb, htid, lane, barid, tstart, tend);
    }
}

// ===================== object MLP + pool + classifier: 1 graph/block, fp16 =====================
#define OB_C   0
#define OB_W   22528
#define OB_H2  67584
#define OB_B1  86016
#define OB_B2  86528
#define OB_B3  87040
#define OB_FCB 87296
#define OB_PT  87328
#define OB_PL  87840
#define OB_SM  88096

__global__ __launch_bounds__(256) void obj_kernel(const float* __restrict__ x,
                                                  const float* __restrict__ b1v,
                                                  const float* __restrict__ b2v,
                                                  const float* __restrict__ b3v,
                                                  const float* __restrict__ fcw,
                                                  const float* __restrict__ fcb,
                                                  float* __restrict__ out)
{
    extern __shared__ char sm[];
    __half* C    = (__half*)(sm + OB_C);
    __half* Wbuf = (__half*)(sm + OB_W);
    __half* H2   = (__half*)(sm + OB_H2);
    __half* H3   = (__half*)(sm + OB_C);          // overlays C, stride 176
    float* bias1  = (float*)(sm + OB_B1);
    float* bias2  = (float*)(sm + OB_B2);
    float* bias3  = (float*)(sm + OB_B3);
    float* fcbs   = (float*)(sm + OB_FCB);
    float* part   = (float*)(sm + OB_PT);
    float* pooled = (float*)(sm + OB_PL);
    const int tid = threadIdx.x, wid = tid >> 5, lane = tid & 31;
    const int g = lane >> 2, tg = lane & 3;
    const int rg = wid & 1, cg = wid >> 1;
    const int bg = blockIdx.x;

    for (int i = tid; i < 2816; i += 256) ((float4*)Wbuf)[i] = ((const float4*)g_FO1)[i];
    if (tid < 128) bias1[tid] = b1v[tid];
    if (tid < 128) bias2[tid] = b2v[tid];
    if (tid < 64)  bias3[tid] = b3v[tid];
    if (tid < 5)   fcbs[tid]  = fcb[tid];
    for (int i = tid; i < 160*64; i += 256){
        int k = i >> 6, n = i & 63;
        float v;
        if (k < 32)      v = x[(bg*32 + k)*64 + n];
        else if (k < 96) v = g_EppT[((size_t)bg*64 + (k-32))*64 + n];
        else             v = g_EpvT[((size_t)bg*64 + (k-96))*64 + n];
        C[n*176 + pp16(k)] = __float2half(v);
    }
    __syncthreads();
    {
        float acc[32];
        wgemm16<10,2,4>(C, 176, Wbuf, 176, rg*32, cg*32, lane, acc);
        epi_store16<2,4>(acc, H2, 144, rg*32, cg*32, lane, bias1);
    }
    __syncthreads();
    for (int i = tid; i < 2304; i += 256) ((float4*)Wbuf)[i] = ((const float4*)g_FO2)[i];
    __syncthreads();
    {
        float acc[32];
        wgemm16<8,2,4>(H2, 144, Wbuf, 144, rg*32, cg*32, lane, acc);
        __syncthreads();
        epi_store16<2,4>(acc, H3, 176, rg*32, cg*32, lane, bias2);
    }
    __syncthreads();
    for (int i = tid; i < 1152; i += 256) ((float4*)Wbuf)[i] = ((const float4*)g_FO3)[i];
    __syncthreads();
    {
        float acc[16];
        wgemm16<8,2,2>(H3, 176, Wbuf, 144, rg*32, cg*16, lane, acc);
#pragma unroll
        for (int nt = 0; nt < 2; nt++){
            int c = cg*16 + nt*8 + tg*2;
            float b0 = bias3[c], b1 = bias3[c+1];
            float t0 = 0.f, t1 = 0.f;
#pragma unroll
            for (int mt = 0; mt < 2; mt++){
                const float* a = acc + (mt*2+nt)*4;
                t0 += fmaxf(a[0]+b0, 0.f) + fmaxf(a[2]+b0, 0.f);
                t1 += fmaxf(a[1]+b1, 0.f) + fmaxf(a[3]+b1, 0.f);
            }
#pragma unroll
            for (int m = 4; m < 32; m <<= 1){
                t0 += __shfl_xor_sync(0xffffffffu, t0, m);
                t1 += __shfl_xor_sync(0xffffffffu, t1, m);
            }
            if (g == 0){ part[rg*64 + c] = t0; part[rg*64 + c + 1] = t1; }
        }
    }
    __syncthreads();
    if (tid < 64) pooled[tid] = part[tid] + part[64 + tid];
    __syncthreads();
    if (tid < 5){
        float s = fcbs[tid];
#pragma unroll 8
        for (int j = 0; j < 64; j++)
            s = fmaf(pooled[j], fcw[j*5 + tid], s);
        out[bg*5 + tid] = s;
    }
}

// ===================== launch =====================
extern "C" void kernel_launch(void* const* d_in, const int* in_sizes, int n_in,
                              void* d_out, int out_size)
{
    const float* x       = (const float*)d_in[0];
    const float* y       = (const float*)d_in[1];
    const float* fr1_w   = (const float*)d_in[2];
    const float* fr1_b   = (const float*)d_in[3];
    const float* fr2_w   = (const float*)d_in[4];
    const float* fr2_b   = (const float*)d_in[5];
    const float* fr3_w   = (const float*)d_in[6];
    const float* fr3_b   = (const float*)d_in[7];
    const float* fr1pv_w = (const float*)d_in[8];
    const float* fr1pv_b = (const float*)d_in[9];
    const float* fr2pv_w = (const float*)d_in[10];
    const float* fr2pv_b = (const float*)d_in[11];
    const float* fr3pv_w = (const float*)d_in[12];
    const float* fr3pv_b = (const float*)d_in[13];
    const float* fo1_w   = (const float*)d_in[14];
    const float* fo1_b   = (const float*)d_in[15];
    const float* fo2_w   = (const float*)d_in[16];
    const float* fo2_b   = (const float*)d_in[17];
    const float* fo3_w   = (const float*)d_in[18];
    const float* fo3_b   = (const float*)d_in[19];
    const float* fc_w    = (const float*)d_in[20];
    const float* fc_b    = (const float*)d_in[21];
    float* out = (float*)d_out;

    cudaFuncSetAttribute(edge_kernel, cudaFuncAttributeMaxDynamicSharedMemorySize, EDGE_SM);
    cudaFuncSetAttribute(obj_kernel,  cudaFuncAttributeMaxDynamicSharedMemorySize, OB_SM);

    init_kernel<<<304, 256>>>(x, y, fr1_w, fr1_b, fr1pv_w, fr1pv_b,
                              fr2_w, fr3_w, fr2pv_w, fr3pv_w, fo1_w, fo2_w, fo3_w);
    edge_kernel<<<152, 512, EDGE_SM>>>(fr2_b, fr3_b, fr2pv_b, fr3pv_b);
    obj_kernel<<<128, 256, OB_SM>>>(x, fo1_b, fo2_b, fo3_b, fc_w, fc_b, out);
}

// round 16
// speedup vs baseline: 1.0524x; 1.0335x over previous
#include <cuda_runtime.h>
#include <cuda_fp16.h>
#include <stdint.h>

#define DI __device__ __forceinline__

// ===================== device scratch (no allocations) =====================
__device__ float g_Upp[128*64*128];
__device__ float g_Vpp[128*64*128];
__device__ float g_Upv[128*64*128];
__device__ float g_Vpv[128*14*128];
__device__ float g_EppT[128*64*64];   // transposed: [b][c][r]
__device__ float g_EpvT[128*64*64];   // transposed: [b][c][r]

// pre-transposed fp16 weight images, pp16-permuted k, stride 144 halves (176 for FO1)
__device__ __align__(16) __half g_W2pp[128*144];
__device__ __align__(16) __half g_W3pp[64*144];
__device__ __align__(16) __half g_W2pv[128*144];
__device__ __align__(16) __half g_W3pv[64*144];
__device__ __align__(16) __half g_FO1 [128*176];
__device__ __align__(16) __half g_FO2 [128*144];
__device__ __align__(16) __half g_FO3 [64*144];

// ===================== helpers =====================
DI int pp16(int k){
    return (k & ~15) | (((k & 7) >> 1) << 2) | (((k >> 3) & 1) << 1) | (k & 1);
}
DI void barh(int id){ asm volatile("bar.sync %0, %1;" :: "r"(id), "r"(256) : "memory"); }

DI void mma_fp16(float* d, uint32_t a0, uint32_t a1, uint32_t a2, uint32_t a3,
                 uint32_t b0, uint32_t b1){
    asm volatile(
        "mma.sync.aligned.m16n8k16.row.col.f32.f16.f16.f32 "
        "{%0,%1,%2,%3}, {%4,%5,%6,%7}, {%8,%9}, {%0,%1,%2,%3};"
        : "+f"(d[0]), "+f"(d[1]), "+f"(d[2]), "+f"(d[3])
        : "r"(a0), "r"(a1), "r"(a2), "r"(a3), "r"(b0), "r"(b1));
}

// Warp GEMM on pp16-interleaved fp16 buffers. KT = K/16.
template<int KT, int MT, int NT>
DI void wgemm16(const __half* A, int sa, const __half* W, int sw,
                int row0, int ncol0, int lane, float* acc)
{
    const int g = lane >> 2, tg = lane & 3;
#pragma unroll
    for (int i = 0; i < MT*NT*4; i++) acc[i] = 0.f;
#pragma unroll
    for (int kt = 0; kt < KT; kt++){
        const int jo = kt*16 + tg*4;
        uint2 av[2*MT];
#pragma unroll
        for (int mt = 0; mt < MT; mt++){
            av[2*mt]   = *(const uint2*)(A + (row0 + mt*16 + g)*sa + jo);
            av[2*mt+1] = *(const uint2*)(A + (row0 + mt*16 + g + 8)*sa + jo);
        }
#pragma unroll
        for (int nt = 0; nt < NT; nt++){
            uint2 bv = *(const uint2*)(W + (ncol0 + nt*8 + g)*sw + jo);
#pragma unroll
            for (int mt = 0; mt < MT; mt++)
                mma_fp16(acc + (mt*NT+nt)*4,
                         av[2*mt].x, av[2*mt+1].x, av[2*mt].y, av[2*mt+1].y,
                         bv.x, bv.y);
        }
    }
}

// Epilogue: relu(acc+bias) -> fp16, stored pp16-permuted into O (stride so halves)
template<int MT, int NT>
DI void epi_store16(const float* acc, __half* O, int so,
                    int row0, int ncol0, int lane, const float* bias)
{
    const int g = lane >> 2, tg = lane & 3;
#pragma unroll
    for (int mt = 0; mt < MT; mt++){
#pragma unroll
        for (int nt = 0; nt < NT; nt++){
            int c0 = ncol0 + nt*8 + 2*tg;
            int q  = pp16(c0);
            float b0 = bias[c0], b1 = bias[c0+1];
            const float* a = acc + (mt*NT+nt)*4;
            int r = row0 + mt*16 + g;
            *(half2*)(O + r*so + q)     = __floats2half2_rn(fmaxf(a[0]+b0, 0.f), fmaxf(a[1]+b1, 0.f));
            *(half2*)(O + (r+8)*so + q) = __floats2half2_rn(fmaxf(a[2]+b0, 0.f), fmaxf(a[3]+b1, 0.f));
        }
    }
}

DI uint2 pack4h(float4 u, float4 v){
    half2 h0 = __floats2half2_rn(fmaxf(u.x+v.x, 0.f), fmaxf(u.y+v.y, 0.f));
    half2 h1 = __floats2half2_rn(fmaxf(u.z+v.z, 0.f), fmaxf(u.w+v.w, 0.f));
    uint2 o; o.x = *(uint32_t*)&h0; o.y = *(uint32_t*)&h1;
    return o;
}

// ===================== init: precompute (256 blocks) + prep (48 blocks) =====================
__global__ __launch_bounds__(256) void init_kernel(
    const float* __restrict__ x, const float* __restrict__ y,
    const float* __restrict__ w1,   const float* __restrict__ b1,
    const float* __restrict__ w1pv, const float* __restrict__ b1pv,
    const float* __restrict__ w2pp, const float* __restrict__ w3pp,
    const float* __restrict__ w2pv, const float* __restrict__ w3pv,
    const float* __restrict__ w1o,  const float* __restrict__ w2o,
    const float* __restrict__ w3o)
{
    const int tid = threadIdx.x;
    if (blockIdx.x < 256){
        // precompute role: block handles (b, nsel) — 32 particles
        __shared__ float xs[32][33];
        const int b = blockIdx.x >> 1, nsel = blockIdx.x & 1, n0 = nsel*32;
        const int h = tid & 127, which = tid >> 7;    // 2 threads per h, 16 n's each
        for (int i = tid; i < 1024; i += 256){
            int p = i >> 5, n = i & 31;
            xs[p][n] = x[(b*32 + p)*64 + n0 + n];
        }
        __syncthreads();
        float u[16], v[16], upv[16];
        const float bu = b1[h], bup = b1pv[h];
#pragma unroll
        for (int i = 0; i < 16; i++){ u[i] = bu; v[i] = 0.f; upv[i] = bup; }
        const int nb = which*16;
#pragma unroll 4
        for (int p = 0; p < 32; p++){
            float wa = w1[p*128 + h];
            float wb = w1[(32+p)*128 + h];
            float wc = w1pv[p*128 + h];
#pragma unroll
            for (int i = 0; i < 16; i++){
                float xv = xs[p][nb + i];
                u[i]   = fmaf(xv, wa, u[i]);
                v[i]   = fmaf(xv, wb, v[i]);
                upv[i] = fmaf(xv, wc, upv[i]);
            }
        }
        const int ph = pp16(h);
#pragma unroll
        for (int i = 0; i < 16; i++){
            int n = n0 + nb + i;
            g_Upp[((size_t)b*64 + n)*128 + ph] = u[i];
            g_Vpp[((size_t)b*64 + n)*128 + ph] = v[i];
            g_Upv[((size_t)b*64 + n)*128 + ph] = upv[i];
        }
        if (nsel == 0){
            float s[7];
#pragma unroll
            for (int j = 0; j < 7; j++) s[j] = 0.f;
#pragma unroll
            for (int sv = 0; sv < 14; sv++){
                float w = w1pv[(32+sv)*128 + h];
#pragma unroll
                for (int j = 0; j < 7; j++)
                    s[j] = fmaf(y[(b*14 + sv)*14 + which*7 + j], w, s[j]);
            }
#pragma unroll
            for (int j = 0; j < 7; j++)
                g_Vpv[((size_t)b*14 + which*7 + j)*128 + ph] = s[j];
        }
    } else {
        // prep role: 48 blocks x 256 threads
        const int T = 48*256, t0 = (blockIdx.x - 256)*256 + tid;
        for (int i = t0; i < 128*128; i += T){ int n = i>>7, k = i&127;
            g_W2pp[n*144 + pp16(k)] = __float2half(w2pp[k*128+n]); }
        for (int i = t0; i < 64*128; i += T){ int n = i>>7, k = i&127;
            g_W3pp[n*144 + pp16(k)] = __float2half(w3pp[k*64+n]); }
        for (int i = t0; i < 128*128; i += T){ int n = i>>7, k = i&127;
            g_W2pv[n*144 + pp16(k)] = __float2half(w2pv[k*128+n]); }
        for (int i = t0; i < 64*128; i += T){ int n = i>>7, k = i&127;
            g_W3pv[n*144 + pp16(k)] = __float2half(w3pv[k*64+n]); }
        for (int i = t0; i < 128*160; i += T){ int n = i/160, k = i - n*160;
            g_FO1[n*176 + pp16(k)] = __float2half(w1o[k*128+n]); }
        for (int i = t0; i < 128*128; i += T){ int n = i>>7, k = i&127;
            g_FO2[n*144 + pp16(k)] = __float2half(w2o[k*128+n]); }
        for (int i = t0; i < 64*128; i += T){ int n = i>>7, k = i&127;
            g_FO3[n*144 + pp16(k)] = __float2half(w3o[k*64+n]); }
    }
}

// ===================== edge kernels: persistent, 512 thr, pipelined half-CTAs =====================
// smem: W2[128x144h] | W3[64x144h] | per-half {H1a,H1b,H2}[64x144h] | b2 | b3 | part 2x128f
#define EP_W2   0
#define EP_W3   36864
#define EP_BUF  55296
#define EP_B2   165888
#define EP_B3   166400
#define EP_PT   166656
#define EP_SM   167680

__global__ __launch_bounds__(512, 1) void pp_kernel(const float* __restrict__ b2v,
                                                    const float* __restrict__ b3v)
{
    extern __shared__ char sm[];
    __half* W2   = (__half*)(sm + EP_W2);
    __half* W3   = (__half*)(sm + EP_W3);
    float* bias2 = (float*)(sm + EP_B2);
    float* bias3 = (float*)(sm + EP_B3);
    const int tid = threadIdx.x;
    const int half_ = tid >> 8, htid = tid & 255;
    const int hw = (tid >> 5) & 7, lane = tid & 31;
    const int g = lane >> 2, tg = lane & 3;
    const int rg = hw & 1, cg = hw >> 1;
    __half* H1a = (__half*)(sm + EP_BUF + half_*55296);
    __half* H1b = (__half*)(sm + EP_BUF + half_*55296 + 18432);
    __half* H2  = (__half*)(sm + EP_BUF + half_*55296 + 36864);
    float* part = (float*)(sm + EP_PT + half_*512);
    const int barid = 1 + half_;

    for (int i = tid; i < 2304; i += 512) ((float4*)W2)[i] = ((const float4*)g_W2pp)[i];
    for (int i = tid; i < 1152; i += 512) ((float4*)W3)[i] = ((const float4*)g_W3pp)[i];
    if (tid < 128) bias2[tid] = b2v[tid];
    if (tid < 64)  bias3[tid] = b3v[tid];
    __syncthreads();

    const int c4 = htid & 31;
    const int r0 = htid >> 5;
    const int hidx = blockIdx.x*2 + half_, nh = gridDim.x*2;
    const int tstart = (int)((long long)8192*hidx/nh);
    const int tend   = (int)((long long)8192*(hidx+1)/nh);

    __half* Hc = H1a;
    __half* Hn = H1b;

    {   // prologue: build tile tstart into Hc
        const int b = tstart >> 6, r = tstart & 63;
        const float* Ur = g_Upp + ((size_t)b*64 + r)*128;
        const float* Vb = g_Vpp + (size_t)b*64*128;
        float4 u = *(const float4*)(Ur + c4*4);
#pragma unroll
        for (int it = 0; it < 8; it++){
            int s = r0 + it*8;
            float4 v = *(const float4*)(Vb + s*128 + c4*4);
            *(uint2*)(Hc + s*144 + c4*4) = pack4h(u, v);
        }
    }
    barh(barid);

    for (int t = tstart; t < tend; t++){
        {
            float acc[32];
            wgemm16<8,2,4>(Hc, 144, W2, 144, rg*32, cg*32, lane, acc);
            epi_store16<2,4>(acc, H2, 144, rg*32, cg*32, lane, bias2);
        }
        barh(barid);

        const bool have_next = (t + 1 < tend);
        float4 u_n; float4 v_n[8];
        if (have_next){
            const int bn = (t+1) >> 6, rn = (t+1) & 63;
            const float* Ur = g_Upp + ((size_t)bn*64 + rn)*128;
            const float* Vb = g_Vpp + (size_t)bn*64*128;
            u_n = *(const float4*)(Ur + c4*4);
#pragma unroll
            for (int it = 0; it < 8; it++)
                v_n[it] = *(const float4*)(Vb + (r0 + it*8)*128 + c4*4);
        }

        float acc3[16];
        wgemm16<8,2,2>(H2, 144, W3, 144, rg*32, cg*16, lane, acc3);

        if (have_next){
#pragma unroll
            for (int it = 0; it < 8; it++)
                *(uint2*)(Hn + (r0 + it*8)*144 + c4*4) = pack4h(u_n, v_n[it]);
        }

        {   // self-excluded column reduce -> part
            const int r = t & 63;
#pragma unroll
            for (int nt = 0; nt < 2; nt++){
                int c = cg*16 + nt*8 + tg*2;
                float b0 = bias3[c], b1 = bias3[c+1];
                float t0 = 0.f, t1 = 0.f;
#pragma unroll
                for (int mt = 0; mt < 2; mt++){
                    int ra = rg*32 + mt*16 + g, rb = ra + 8;
                    bool z1 = (ra == r), z2 = (rb == r);
                    const float* a = acc3 + (mt*2+nt)*4;
                    t0 += (z1 ? 0.f : fmaxf(a[0]+b0, 0.f)) + (z2 ? 0.f : fmaxf(a[2]+b0, 0.f));
                    t1 += (z1 ? 0.f : fmaxf(a[1]+b1, 0.f)) + (z2 ? 0.f : fmaxf(a[3]+b1, 0.f));
                }
#pragma unroll
                for (int m = 4; m < 32; m <<= 1){
                    t0 += __shfl_xor_sync(0xffffffffu, t0, m);
                    t1 += __shfl_xor_sync(0xffffffffu, t1, m);
                }
                if (g == 0){ part[rg*64 + c] = t0; part[rg*64 + c + 1] = t1; }
            }
        }
        barh(barid);
        if (htid < 64){
            const int b = t >> 6, r = t & 63;
            g_EppT[((size_t)b*64 + htid)*64 + r] = part[htid] + part[64 + htid];
        }
        __half* tmp = Hc; Hc = Hn; Hn = tmp;
    }
}

__global__ __launch_bounds__(512, 1) void pv_kernel(const float* __restrict__ b2v,
                                                    const float* __restrict__ b3v)
{
    extern __shared__ char sm[];
    __half* W2   = (__half*)(sm + EP_W2);
    __half* W3   = (__half*)(sm + EP_W3);
    float* bias2 = (float*)(sm + EP_B2);
    float* bias3 = (float*)(sm + EP_B3);
    const int tid = threadIdx.x;
    const int half_ = tid >> 8, htid = tid & 255;
    const int hw = (tid >> 5) & 7, lane = tid & 31;
    const int g = lane >> 2, tg = lane & 3;
    const int rg = hw & 1, cg = hw >> 1;
    __half* H1a = (__half*)(sm + EP_BUF + half_*55296);
    __half* H1b = (__half*)(sm + EP_BUF + half_*55296 + 18432);
    __half* H2  = (__half*)(sm + EP_BUF + half_*55296 + 36864);
    const int barid = 1 + half_;

    for (int i = tid; i < 2304; i += 512) ((float4*)W2)[i] = ((const float4*)g_W2pv)[i];
    for (int i = tid; i < 1152; i += 512) ((float4*)W3)[i] = ((const float4*)g_W3pv)[i];
    if (tid < 128) bias2[tid] = b2v[tid];
    if (tid < 64)  bias3[tid] = b3v[tid];
    __syncthreads();

    const int c4 = htid & 31;
    const int r0 = htid >> 5;
    const int hidx = blockIdx.x*2 + half_, nh = gridDim.x*2;
    const int tstart = (int)((long long)2048*hidx/nh);
    const int tend   = (int)((long long)2048*(hidx+1)/nh);

    __half* Hc = H1a;
    __half* Hn = H1b;

    {   // prologue build: rows = 4 receivers x 16 slots (vv>=14 pad -> 0)
        const int b = tstart >> 4, grp = tstart & 15;
        const float* Ub = g_Upv + ((size_t)b*64 + grp*4)*128;
        const float* Vb = g_Vpv + (size_t)b*14*128;
#pragma unroll
        for (int it = 0; it < 8; it++){
            int row = r0 + it*8;
            int ri = row >> 4, vv = row & 15;
            uint2 o; o.x = 0u; o.y = 0u;
            if (vv < 14)
                o = pack4h(*(const float4*)(Ub + ri*128 + c4*4),
                           *(const float4*)(Vb + vv*128 + c4*4));
            *(uint2*)(Hc + row*144 + c4*4) = o;
        }
    }
    barh(barid);

    for (int t = tstart; t < tend; t++){
        {
            float acc[32];
            wgemm16<8,2,4>(Hc, 144, W2, 144, rg*32, cg*32, lane, acc);
            epi_store16<2,4>(acc, H2, 144, rg*32, cg*32, lane, bias2);
        }
        barh(barid);

        const bool have_next = (t + 1 < tend);
        float4 u_n[8]; float4 v_n[8]; bool valid[8];
        if (have_next){
            const int bn = (t+1) >> 4, gn = (t+1) & 15;
            const float* Ub = g_Upv + ((size_t)bn*64 + gn*4)*128;
            const float* Vb = g_Vpv + (size_t)bn*14*128;
#pragma unroll
            for (int it = 0; it < 8; it++){
                int row = r0 + it*8;
                int ri = row >> 4, vv = row & 15;
                valid[it] = (vv < 14);
                if (valid[it]){
                    u_n[it] = *(const float4*)(Ub + ri*128 + c4*4);
                    v_n[it] = *(const float4*)(Vb + vv*128 + c4*4);
                }
            }
        }

        float acc3[16];
        wgemm16<8,2,2>(H2, 144, W3, 144, rg*32, cg*16, lane, acc3);

        if (have_next){
#pragma unroll
            for (int it = 0; it < 8; it++){
                int row = r0 + it*8;
                uint2 o; o.x = 0u; o.y = 0u;
                if (valid[it]) o = pack4h(u_n[it], v_n[it]);
                *(uint2*)(Hn + row*144 + c4*4) = o;
            }
        }

        {   // per-receiver reduce (receiver = grp*4 + rg*2 + mt), direct to gmem
            const int b = t >> 4, grp = t & 15;
            bool z2 = (g >= 6);
#pragma unroll
            for (int mt = 0; mt < 2; mt++){
                int recv = grp*4 + rg*2 + mt;
#pragma unroll
                for (int nt = 0; nt < 2; nt++){
                    int c = cg*16 + nt*8 + tg*2;
                    float b0 = bias3[c], b1 = bias3[c+1];
                    const float* a = acc3 + (mt*2+nt)*4;
                    float t0 = fmaxf(a[0]+b0, 0.f) + (z2 ? 0.f : fmaxf(a[2]+b0, 0.f));
                    float t1 = fmaxf(a[1]+b1, 0.f) + (z2 ? 0.f : fmaxf(a[3]+b1, 0.f));
#pragma unroll
                    for (int m = 4; m < 32; m <<= 1){
                        t0 += __shfl_xor_sync(0xffffffffu, t0, m);
                        t1 += __shfl_xor_sync(0xffffffffu, t1, m);
                    }
                    if (g == 0){
                        g_EpvT[((size_t)b*64 + c)*64 + recv]     = t0;
                        g_EpvT[((size_t)b*64 + c + 1)*64 + recv] = t1;
                    }
                }
            }
        }
        barh(barid);
        __half* tmp = Hc; Hc = Hn; Hn = tmp;
    }
}

// ===================== object MLP + pool + classifier: 1 graph/block, fp16 =====================
#define OB_C   0
#define OB_W   22528
#define OB_H2  67584
#define OB_B1  86016
#define OB_B2  86528
#define OB_B3  87040
#define OB_FCB 87296
#define OB_PT  87328
#define OB_PL  87840
#define OB_SM  88096

__global__ __launch_bounds__(256) void obj_kernel(const float* __restrict__ x,
                                                  const float* __restrict__ b1v,
                                                  const float* __restrict__ b2v,
                                                  const float* __restrict__ b3v,
                                                  const float* __restrict__ fcw,
                                                  const float* __restrict__ fcb,
                                                  float* __restrict__ out)
{
    extern __shared__ char sm[];
    __half* C    = (__half*)(sm + OB_C);
    __half* Wbuf = (__half*)(sm + OB_W);
    __half* H2   = (__half*)(sm + OB_H2);
    __half* H3   = (__half*)(sm + OB_C);          // overlays C, stride 176
    float* bias1  = (float*)(sm + OB_B1);
    float* bias2  = (float*)(sm + OB_B2);
    float* bias3  = (float*)(sm + OB_B3);
    float* fcbs   = (float*)(sm + OB_FCB);
    float* part   = (float*)(sm + OB_PT);
    float* pooled = (float*)(sm + OB_PL);
    const int tid = threadIdx.x, wid = tid >> 5, lane = tid & 31;
    const int g = lane >> 2, tg = lane & 3;
    const int rg = wid & 1, cg = wid >> 1;
    const int bg = blockIdx.x;

    for (int i = tid; i < 2816; i += 256) ((float4*)Wbuf)[i] = ((const float4*)g_FO1)[i];
    if (tid < 128) bias1[tid] = b1v[tid];
    if (tid < 128) bias2[tid] = b2v[tid];
    if (tid < 64)  bias3[tid] = b3v[tid];
    if (tid < 5)   fcbs[tid]  = fcb[tid];
    for (int i = tid; i < 160*64; i += 256){
        int k = i >> 6, n = i & 63;
        float v;
        if (k < 32)      v = x[(bg*32 + k)*64 + n];
        else if (k < 96) v = g_EppT[((size_t)bg*64 + (k-32))*64 + n];
        else             v = g_EpvT[((size_t)bg*64 + (k-96))*64 + n];
        C[n*176 + pp16(k)] = __float2half(v);
    }
    __syncthreads();
    {
        float acc[32];
        wgemm16<10,2,4>(C, 176, Wbuf, 176, rg*32, cg*32, lane, acc);
        epi_store16<2,4>(acc, H2, 144, rg*32, cg*32, lane, bias1);
    }
    __syncthreads();
    for (int i = tid; i < 2304; i += 256) ((float4*)Wbuf)[i] = ((const float4*)g_FO2)[i];
    __syncthreads();
    {
        float acc[32];
        wgemm16<8,2,4>(H2, 144, Wbuf, 144, rg*32, cg*32, lane, acc);
        __syncthreads();
        epi_store16<2,4>(acc, H3, 176, rg*32, cg*32, lane, bias2);
    }
    __syncthreads();
    for (int i = tid; i < 1152; i += 256) ((float4*)Wbuf)[i] = ((const float4*)g_FO3)[i];
    __syncthreads();
    {
        float acc[16];
        wgemm16<8,2,2>(H3, 176, Wbuf, 144, rg*32, cg*16, lane, acc);
#pragma unroll
        for (int nt = 0; nt < 2; nt++){
            int c = cg*16 + nt*8 + tg*2;
            float b0 = bias3[c], b1 = bias3[c+1];
            float t0 = 0.f, t1 = 0.f;
#pragma unroll
            for (int mt = 0; mt < 2; mt++){
                const float* a = acc + (mt*2+nt)*4;
                t0 += fmaxf(a[0]+b0, 0.f) + fmaxf(a[2]+b0, 0.f);
                t1 += fmaxf(a[1]+b1, 0.f) + fmaxf(a[3]+b1, 0.f);
            }
#pragma unroll
            for (int m = 4; m < 32; m <<= 1){
                t0 += __shfl_xor_sync(0xffffffffu, t0, m);
                t1 += __shfl_xor_sync(0xffffffffu, t1, m);
            }
            if (g == 0){ part[rg*64 + c] = t0; part[rg*64 + c + 1] = t1; }
        }
    }
    __syncthreads();
    if (tid < 64) pooled[tid] = part[tid] + part[64 + tid];
    __syncthreads();
    if (tid < 5){
        float s = fcbs[tid];
#pragma unroll 8
        for (int j = 0; j < 64; j++)
            s = fmaf(pooled[j], fcw[j*5 + tid], s);
        out[bg*5 + tid] = s;
    }
}

// ===================== launch =====================
extern "C" void kernel_launch(void* const* d_in, const int* in_sizes, int n_in,
                              void* d_out, int out_size)
{
    const float* x       = (const float*)d_in[0];
    const float* y       = (const float*)d_in[1];
    const float* fr1_w   = (const float*)d_in[2];
    const float* fr1_b   = (const float*)d_in[3];
    const float* fr2_w   = (const float*)d_in[4];
    const float* fr2_b   = (const float*)d_in[5];
    const float* fr3_w   = (const float*)d_in[6];
    const float* fr3_b   = (const float*)d_in[7];
    const float* fr1pv_w = (const float*)d_in[8];
    const float* fr1pv_b = (const float*)d_in[9];
    const float* fr2pv_w = (const float*)d_in[10];
    const float* fr2pv_b = (const float*)d_in[11];
    const float* fr3pv_w = (const float*)d_in[12];
    const float* fr3pv_b = (const float*)d_in[13];
    const float* fo1_w   = (const float*)d_in[14];
    const float* fo1_b   = (const float*)d_in[15];
    const float* fo2_w   = (const float*)d_in[16];
    const float* fo2_b   = (const float*)d_in[17];
    const float* fo3_w   = (const float*)d_in[18];
    const float* fo3_b   = (const float*)d_in[19];
    const float* fc_w    = (const float*)d_in[20];
    const float* fc_b    = (const float*)d_in[21];
    float* out = (float*)d_out;

    cudaFuncSetAttribute(pp_kernel,  cudaFuncAttributeMaxDynamicSharedMemorySize, EP_SM);
    cudaFuncSetAttribute(pv_kernel,  cudaFuncAttributeMaxDynamicSharedMemorySize, EP_SM);
    cudaFuncSetAttribute(obj_kernel, cudaFuncAttributeMaxDynamicSharedMemorySize, OB_SM);

    init_kernel<<<304, 256>>>(x, y, fr1_w, fr1_b, fr1pv_w, fr1pv_b,
                              fr2_w, fr3_w, fr2pv_w, fr3pv_w, fo1_w, fo2_w, fo3_w);
    pp_kernel<<<152, 512, EP_SM>>>(fr2_b, fr3_b);
    pv_kernel<<<152, 512, EP_SM>>>(fr2pv_b, fr3pv_b);
    obj_kernel<<<128, 256, OB_SM>>>(x, fo1_b, fo2_b, fo3_b, fc_w, fc_b, out);
}

// round 17
// speedup vs baseline: 1.0715x; 1.0182x over previous
#include <cuda_runtime.h>
#include <cuda_fp16.h>
#include <stdint.h>

#define DI __device__ __forceinline__

// ===================== device scratch (no allocations) =====================
__device__ float g_Upp[128*64*128];
__device__ float g_Vpp[128*64*128];
__device__ float g_Upv[128*64*128];
__device__ float g_Vpv[128*14*128];
__device__ float g_EppT[128*64*64];   // transposed: [b][c][r]
__device__ float g_EpvT[128*64*64];   // transposed: [b][c][r]

// pre-transposed fp16 weight images, pp16-permuted k, stride 144 halves (176 for FO1)
__device__ __align__(16) __half g_W2pp[128*144];
__device__ __align__(16) __half g_W3pp[64*144];
__device__ __align__(16) __half g_W2pv[128*144];
__device__ __align__(16) __half g_W3pv[64*144];
__device__ __align__(16) __half g_FO1 [128*176];
__device__ __align__(16) __half g_FO2 [128*144];
__device__ __align__(16) __half g_FO3 [64*144];

// ===================== helpers =====================
DI int pp16(int k){
    return (k & ~15) | (((k & 7) >> 1) << 2) | (((k >> 3) & 1) << 1) | (k & 1);
}
DI void barh(int id){ asm volatile("bar.sync %0, %1;" :: "r"(id), "r"(256) : "memory"); }

DI void mma_fp16(float* d, uint32_t a0, uint32_t a1, uint32_t a2, uint32_t a3,
                 uint32_t b0, uint32_t b1){
    asm volatile(
        "mma.sync.aligned.m16n8k16.row.col.f32.f16.f16.f32 "
        "{%0,%1,%2,%3}, {%4,%5,%6,%7}, {%8,%9}, {%0,%1,%2,%3};"
        : "+f"(d[0]), "+f"(d[1]), "+f"(d[2]), "+f"(d[3])
        : "r"(a0), "r"(a1), "r"(a2), "r"(a3), "r"(b0), "r"(b1));
}

// Warp GEMM on pp16-interleaved fp16 buffers. KT = K/16.
template<int KT, int MT, int NT>
DI void wgemm16(const __half* A, int sa, const __half* W, int sw,
                int row0, int ncol0, int lane, float* acc)
{
    const int g = lane >> 2, tg = lane & 3;
#pragma unroll
    for (int i = 0; i < MT*NT*4; i++) acc[i] = 0.f;
#pragma unroll
    for (int kt = 0; kt < KT; kt++){
        const int jo = kt*16 + tg*4;
        uint2 av[2*MT];
#pragma unroll
        for (int mt = 0; mt < MT; mt++){
            av[2*mt]   = *(const uint2*)(A + (row0 + mt*16 + g)*sa + jo);
            av[2*mt+1] = *(const uint2*)(A + (row0 + mt*16 + g + 8)*sa + jo);
        }
#pragma unroll
        for (int nt = 0; nt < NT; nt++){
            uint2 bv = *(const uint2*)(W + (ncol0 + nt*8 + g)*sw + jo);
#pragma unroll
            for (int mt = 0; mt < MT; mt++)
                mma_fp16(acc + (mt*NT+nt)*4,
                         av[2*mt].x, av[2*mt+1].x, av[2*mt].y, av[2*mt+1].y,
                         bv.x, bv.y);
        }
    }
}

// Epilogue: relu(acc+bias) -> fp16, stored pp16-permuted into O (stride so halves)
template<int MT, int NT>
DI void epi_store16(const float* acc, __half* O, int so,
                    int row0, int ncol0, int lane, const float* bias)
{
    const int g = lane >> 2, tg = lane & 3;
#pragma unroll
    for (int mt = 0; mt < MT; mt++){
#pragma unroll
        for (int nt = 0; nt < NT; nt++){
            int c0 = ncol0 + nt*8 + 2*tg;
            int q  = pp16(c0);
            float b0 = bias[c0], b1 = bias[c0+1];
            const float* a = acc + (mt*NT+nt)*4;
            int r = row0 + mt*16 + g;
            *(half2*)(O + r*so + q)     = __floats2half2_rn(fmaxf(a[0]+b0, 0.f), fmaxf(a[1]+b1, 0.f));
            *(half2*)(O + (r+8)*so + q) = __floats2half2_rn(fmaxf(a[2]+b0, 0.f), fmaxf(a[3]+b1, 0.f));
        }
    }
}

DI uint2 pack4h(float4 u, float4 v){
    half2 h0 = __floats2half2_rn(fmaxf(u.x+v.x, 0.f), fmaxf(u.y+v.y, 0.f));
    half2 h1 = __floats2half2_rn(fmaxf(u.z+v.z, 0.f), fmaxf(u.w+v.w, 0.f));
    uint2 o; o.x = *(uint32_t*)&h0; o.y = *(uint32_t*)&h1;
    return o;
}

// ===================== init: precompute (256 blocks) + prep (48 blocks) =====================
__global__ __launch_bounds__(256) void init_kernel(
    const float* __restrict__ x, const float* __restrict__ y,
    const float* __restrict__ w1,   const float* __restrict__ b1,
    const float* __restrict__ w1pv, const float* __restrict__ b1pv,
    const float* __restrict__ w2pp, const float* __restrict__ w3pp,
    const float* __restrict__ w2pv, const float* __restrict__ w3pv,
    const float* __restrict__ w1o,  const float* __restrict__ w2o,
    const float* __restrict__ w3o)
{
    const int tid = threadIdx.x;
    if (blockIdx.x < 256){
        __shared__ float xs[32][33];
        const int b = blockIdx.x >> 1, nsel = blockIdx.x & 1, n0 = nsel*32;
        const int h = tid & 127, which = tid >> 7;
        for (int i = tid; i < 1024; i += 256){
            int p = i >> 5, n = i & 31;
            xs[p][n] = x[(b*32 + p)*64 + n0 + n];
        }
        __syncthreads();
        float u[16], v[16], upv[16];
        const float bu = b1[h], bup = b1pv[h];
#pragma unroll
        for (int i = 0; i < 16; i++){ u[i] = bu; v[i] = 0.f; upv[i] = bup; }
        const int nb = which*16;
#pragma unroll 4
        for (int p = 0; p < 32; p++){
            float wa = w1[p*128 + h];
            float wb = w1[(32+p)*128 + h];
            float wc = w1pv[p*128 + h];
#pragma unroll
            for (int i = 0; i < 16; i++){
                float xv = xs[p][nb + i];
                u[i]   = fmaf(xv, wa, u[i]);
                v[i]   = fmaf(xv, wb, v[i]);
                upv[i] = fmaf(xv, wc, upv[i]);
            }
        }
        const int ph = pp16(h);
#pragma unroll
        for (int i = 0; i < 16; i++){
            int n = n0 + nb + i;
            g_Upp[((size_t)b*64 + n)*128 + ph] = u[i];
            g_Vpp[((size_t)b*64 + n)*128 + ph] = v[i];
            g_Upv[((size_t)b*64 + n)*128 + ph] = upv[i];
        }
        if (nsel == 0){
            float s[7];
#pragma unroll
            for (int j = 0; j < 7; j++) s[j] = 0.f;
#pragma unroll
            for (int sv = 0; sv < 14; sv++){
                float w = w1pv[(32+sv)*128 + h];
#pragma unroll
                for (int j = 0; j < 7; j++)
                    s[j] = fmaf(y[(b*14 + sv)*14 + which*7 + j], w, s[j]);
            }
#pragma unroll
            for (int j = 0; j < 7; j++)
                g_Vpv[((size_t)b*14 + which*7 + j)*128 + ph] = s[j];
        }
    } else {
        const int T = 48*256, t0 = (blockIdx.x - 256)*256 + tid;
        for (int i = t0; i < 128*128; i += T){ int n = i>>7, k = i&127;
            g_W2pp[n*144 + pp16(k)] = __float2half(w2pp[k*128+n]); }
        for (int i = t0; i < 64*128; i += T){ int n = i>>7, k = i&127;
            g_W3pp[n*144 + pp16(k)] = __float2half(w3pp[k*64+n]); }
        for (int i = t0; i < 128*128; i += T){ int n = i>>7, k = i&127;
            g_W2pv[n*144 + pp16(k)] = __float2half(w2pv[k*128+n]); }
        for (int i = t0; i < 64*128; i += T){ int n = i>>7, k = i&127;
            g_W3pv[n*144 + pp16(k)] = __float2half(w3pv[k*64+n]); }
        for (int i = t0; i < 128*160; i += T){ int n = i/160, k = i - n*160;
            g_FO1[n*176 + pp16(k)] = __float2half(w1o[k*128+n]); }
        for (int i = t0; i < 128*128; i += T){ int n = i>>7, k = i&127;
            g_FO2[n*144 + pp16(k)] = __float2half(w2o[k*128+n]); }
        for (int i = t0; i < 64*128; i += T){ int n = i>>7, k = i&127;
            g_FO3[n*144 + pp16(k)] = __float2half(w3o[k*64+n]); }
    }
}

// ===================== edge kernels: persistent, 512 thr, pipelined half-CTAs =====================
#define EP_W2   0
#define EP_W3   36864
#define EP_BUF  55296
#define EP_B2   165888
#define EP_B3   166400
#define EP_PT   166656
#define EP_SM   167680

__global__ __launch_bounds__(512, 1) void pp_kernel(const float* __restrict__ b2v,
                                                    const float* __restrict__ b3v)
{
    extern __shared__ char sm[];
    __half* W2   = (__half*)(sm + EP_W2);
    __half* W3   = (__half*)(sm + EP_W3);
    float* bias2 = (float*)(sm + EP_B2);
    float* bias3 = (float*)(sm + EP_B3);
    const int tid = threadIdx.x;
    const int half_ = tid >> 8, htid = tid & 255;
    const int hw = (tid >> 5) & 7, lane = tid & 31;
    const int g = lane >> 2, tg = lane & 3;
    const int rg = hw & 1, cg = hw >> 1;
    __half* H1a = (__half*)(sm + EP_BUF + half_*55296);
    __half* H1b = (__half*)(sm + EP_BUF + half_*55296 + 18432);
    __half* H2  = (__half*)(sm + EP_BUF + half_*55296 + 36864);
    float* part = (float*)(sm + EP_PT + half_*512);
    const int barid = 1 + half_;

    for (int i = tid; i < 2304; i += 512) ((float4*)W2)[i] = ((const float4*)g_W2pp)[i];
    for (int i = tid; i < 1152; i += 512) ((float4*)W3)[i] = ((const float4*)g_W3pp)[i];
    if (tid < 128) bias2[tid] = b2v[tid];
    if (tid < 64)  bias3[tid] = b3v[tid];
    __syncthreads();

    const int c4 = htid & 31;
    const int r0 = htid >> 5;
    const int hidx = blockIdx.x*2 + half_, nh = gridDim.x*2;
    const int tstart = (int)((long long)8192*hidx/nh);
    const int tend   = (int)((long long)8192*(hidx+1)/nh);

    __half* Hc = H1a;
    __half* Hn = H1b;

    {
        const int b = tstart >> 6, r = tstart & 63;
        const float* Ur = g_Upp + ((size_t)b*64 + r)*128;
        const float* Vb = g_Vpp + (size_t)b*64*128;
        float4 u = *(const float4*)(Ur + c4*4);
#pragma unroll
        for (int it = 0; it < 8; it++){
            int s = r0 + it*8;
            float4 v = *(const float4*)(Vb + s*128 + c4*4);
            *(uint2*)(Hc + s*144 + c4*4) = pack4h(u, v);
        }
    }
    barh(barid);

    for (int t = tstart; t < tend; t++){
        {
            float acc[32];
            wgemm16<8,2,4>(Hc, 144, W2, 144, rg*32, cg*32, lane, acc);
            epi_store16<2,4>(acc, H2, 144, rg*32, cg*32, lane, bias2);
        }
        barh(barid);

        const bool have_next = (t + 1 < tend);
        float4 u_n; float4 v_n[8];
        if (have_next){
            const int bn = (t+1) >> 6, rn = (t+1) & 63;
            const float* Ur = g_Upp + ((size_t)bn*64 + rn)*128;
            const float* Vb = g_Vpp + (size_t)bn*64*128;
            u_n = *(const float4*)(Ur + c4*4);
#pragma unroll
            for (int it = 0; it < 8; it++)
                v_n[it] = *(const float4*)(Vb + (r0 + it*8)*128 + c4*4);
        }

        float acc3[16];
        wgemm16<8,2,2>(H2, 144, W3, 144, rg*32, cg*16, lane, acc3);

        if (have_next){
#pragma unroll
            for (int it = 0; it < 8; it++)
                *(uint2*)(Hn + (r0 + it*8)*144 + c4*4) = pack4h(u_n, v_n[it]);
        }

        {
            const int r = t & 63;
#pragma unroll
            for (int nt = 0; nt < 2; nt++){
                int c = cg*16 + nt*8 + tg*2;
                float b0 = bias3[c], b1 = bias3[c+1];
                float t0 = 0.f, t1 = 0.f;
#pragma unroll
                for (int mt = 0; mt < 2; mt++){
                    int ra = rg*32 + mt*16 + g, rb = ra + 8;
                    bool z1 = (ra == r), z2 = (rb == r);
                    const float* a = acc3 + (mt*2+nt)*4;
                    t0 += (z1 ? 0.f : fmaxf(a[0]+b0, 0.f)) + (z2 ? 0.f : fmaxf(a[2]+b0, 0.f));
                    t1 += (z1 ? 0.f : fmaxf(a[1]+b1, 0.f)) + (z2 ? 0.f : fmaxf(a[3]+b1, 0.f));
                }
#pragma unroll
                for (int m = 4; m < 32; m <<= 1){
                    t0 += __shfl_xor_sync(0xffffffffu, t0, m);
                    t1 += __shfl_xor_sync(0xffffffffu, t1, m);
                }
                if (g == 0){ part[rg*64 + c] = t0; part[rg*64 + c + 1] = t1; }
            }
        }
        barh(barid);
        if (htid < 64){
            const int b = t >> 6, r = t & 63;
            g_EppT[((size_t)b*64 + htid)*64 + r] = part[htid] + part[64 + htid];
        }
        __half* tmp = Hc; Hc = Hn; Hn = tmp;
    }
}

__global__ __launch_bounds__(512, 1) void pv_kernel(const float* __restrict__ b2v,
                                                    const float* __restrict__ b3v)
{
    extern __shared__ char sm[];
    __half* W2   = (__half*)(sm + EP_W2);
    __half* W3   = (__half*)(sm + EP_W3);
    float* bias2 = (float*)(sm + EP_B2);
    float* bias3 = (float*)(sm + EP_B3);
    const int tid = threadIdx.x;
    const int half_ = tid >> 8, htid = tid & 255;
    const int hw = (tid >> 5) & 7, lane = tid & 31;
    const int g = lane >> 2, tg = lane & 3;
    const int rg = hw & 1, cg = hw >> 1;
    __half* H1a = (__half*)(sm + EP_BUF + half_*55296);
    __half* H1b = (__half*)(sm + EP_BUF + half_*55296 + 18432);
    __half* H2  = (__half*)(sm + EP_BUF + half_*55296 + 36864);
    const int barid = 1 + half_;

    for (int i = tid; i < 2304; i += 512) ((float4*)W2)[i] = ((const float4*)g_W2pv)[i];
    for (int i = tid; i < 1152; i += 512) ((float4*)W3)[i] = ((const float4*)g_W3pv)[i];
    if (tid < 128) bias2[tid] = b2v[tid];
    if (tid < 64)  bias3[tid] = b3v[tid];
    __syncthreads();

    const int c4 = htid & 31;
    const int r0 = htid >> 5;
    const int hidx = blockIdx.x*2 + half_, nh = gridDim.x*2;
    const int tstart = (int)((long long)2048*hidx/nh);
    const int tend   = (int)((long long)2048*(hidx+1)/nh);

    __half* Hc = H1a;
    __half* Hn = H1b;

    {
        const int b = tstart >> 4, grp = tstart & 15;
        const float* Ub = g_Upv + ((size_t)b*64 + grp*4)*128;
        const float* Vb = g_Vpv + (size_t)b*14*128;
#pragma unroll
        for (int it = 0; it < 8; it++){
            int row = r0 + it*8;
            int ri = row >> 4, vv = row & 15;
            uint2 o; o.x = 0u; o.y = 0u;
            if (vv < 14)
                o = pack4h(*(const float4*)(Ub + ri*128 + c4*4),
                           *(const float4*)(Vb + vv*128 + c4*4));
            *(uint2*)(Hc + row*144 + c4*4) = o;
        }
    }
    barh(barid);

    for (int t = tstart; t < tend; t++){
        {
            float acc[32];
            wgemm16<8,2,4>(Hc, 144, W2, 144, rg*32, cg*32, lane, acc);
            epi_store16<2,4>(acc, H2, 144, rg*32, cg*32, lane, bias2);
        }
        barh(barid);

        const bool have_next = (t + 1 < tend);
        float4 u_n[8]; float4 v_n[8]; bool valid[8];
        if (have_next){
            const int bn = (t+1) >> 4, gn = (t+1) & 15;
            const float* Ub = g_Upv + ((size_t)bn*64 + gn*4)*128;
            const float* Vb = g_Vpv + (size_t)bn*14*128;
#pragma unroll
            for (int it = 0; it < 8; it++){
                int row = r0 + it*8;
                int ri = row >> 4, vv = row & 15;
                valid[it] = (vv < 14);
                if (valid[it]){
                    u_n[it] = *(const float4*)(Ub + ri*128 + c4*4);
                    v_n[it] = *(const float4*)(Vb + vv*128 + c4*4);
                }
            }
        }

        float acc3[16];
        wgemm16<8,2,2>(H2, 144, W3, 144, rg*32, cg*16, lane, acc3);

        if (have_next){
#pragma unroll
            for (int it = 0; it < 8; it++){
                int row = r0 + it*8;
                uint2 o; o.x = 0u; o.y = 0u;
                if (valid[it]) o = pack4h(u_n[it], v_n[it]);
                *(uint2*)(Hn + row*144 + c4*4) = o;
            }
        }

        {
            const int b = t >> 4, grp = t & 15;
            bool z2 = (g >= 6);
#pragma unroll
            for (int mt = 0; mt < 2; mt++){
                int recv = grp*4 + rg*2 + mt;
#pragma unroll
                for (int nt = 0; nt < 2; nt++){
                    int c = cg*16 + nt*8 + tg*2;
                    float b0 = bias3[c], b1 = bias3[c+1];
                    const float* a = acc3 + (mt*2+nt)*4;
                    float t0 = fmaxf(a[0]+b0, 0.f) + (z2 ? 0.f : fmaxf(a[2]+b0, 0.f));
                    float t1 = fmaxf(a[1]+b1, 0.f) + (z2 ? 0.f : fmaxf(a[3]+b1, 0.f));
#pragma unroll
                    for (int m = 4; m < 32; m <<= 1){
                        t0 += __shfl_xor_sync(0xffffffffu, t0, m);
                        t1 += __shfl_xor_sync(0xffffffffu, t1, m);
                    }
                    if (g == 0){
                        g_EpvT[((size_t)b*64 + c)*64 + recv]     = t0;
                        g_EpvT[((size_t)b*64 + c + 1)*64 + recv] = t1;
                    }
                }
            }
        }
        barh(barid);
        __half* tmp = Hc; Hc = Hn; Hn = tmp;
    }
}

// ===================== object MLP: 512 thr, all weights staged up-front =====================
// C[64x176h]=22528 | FO1[128x176h]=45056 | FO2[128x144h]=36864 | FO3[64x144h]=18432
// | H2[64x144h]=18432 | b1 | b2 | b3 | fcb | part[4x64f] | pooled ; H3 overlays C
#define OB_C    0
#define OB_W1   22528
#define OB_W2o  67584
#define OB_W3o  104448
#define OB_H2   122880
#define OB_B1   141312
#define OB_B2   141824
#define OB_B3   142336
#define OB_FCB  142592
#define OB_PT   142624
#define OB_PL   143648
#define OB_SM   143904

__global__ __launch_bounds__(512, 1) void obj_kernel(const float* __restrict__ x,
                                                     const float* __restrict__ b1v,
                                                     const float* __restrict__ b2v,
                                                     const float* __restrict__ b3v,
                                                     const float* __restrict__ fcw,
                                                     const float* __restrict__ fcb,
                                                     float* __restrict__ out)
{
    extern __shared__ char sm[];
    __half* C    = (__half*)(sm + OB_C);
    __half* FO1  = (__half*)(sm + OB_W1);
    __half* FO2  = (__half*)(sm + OB_W2o);
    __half* FO3  = (__half*)(sm + OB_W3o);
    __half* H2   = (__half*)(sm + OB_H2);
    __half* H3   = (__half*)(sm + OB_C);          // overlays C, stride 176
    float* bias1  = (float*)(sm + OB_B1);
    float* bias2  = (float*)(sm + OB_B2);
    float* bias3  = (float*)(sm + OB_B3);
    float* fcbs   = (float*)(sm + OB_FCB);
    float* part   = (float*)(sm + OB_PT);
    float* pooled = (float*)(sm + OB_PL);
    const int tid = threadIdx.x, wid = tid >> 5, lane = tid & 31;
    const int g = lane >> 2, tg = lane & 3;
    const int rg = wid & 3, cg = wid >> 2;        // 4 row groups x 4 col groups
    const int bg = blockIdx.x;

    // stage EVERYTHING up-front: all 3 weight buffers + biases + C
    for (int i = tid; i < 2816; i += 512) ((float4*)FO1)[i] = ((const float4*)g_FO1)[i];
    for (int i = tid; i < 2304; i += 512) ((float4*)FO2)[i] = ((const float4*)g_FO2)[i];
    for (int i = tid; i < 1152; i += 512) ((float4*)FO3)[i] = ((const float4*)g_FO3)[i];
    if (tid < 128) bias1[tid] = b1v[tid];
    else if (tid < 256) bias2[tid-128] = b2v[tid-128];
    else if (tid < 320) bias3[tid-256] = b3v[tid-256];
    else if (tid < 325) fcbs[tid-320]  = fcb[tid-320];
    for (int i = tid; i < 160*64; i += 512){
        int k = i >> 6, n = i & 63;
        float v;
        if (k < 32)      v = x[(bg*32 + k)*64 + n];
        else if (k < 96) v = g_EppT[((size_t)bg*64 + (k-32))*64 + n];
        else             v = g_EpvT[((size_t)bg*64 + (k-96))*64 + n];
        C[n*176 + pp16(k)] = __float2half(v);
    }
    __syncthreads();
    {   // layer 1: H2 = relu(C @ FO1^T + b1)
        float acc[16];
        wgemm16<10,1,4>(C, 176, FO1, 176, rg*16, cg*32, lane, acc);
        epi_store16<1,4>(acc, H2, 144, rg*16, cg*32, lane, bias1);
    }
    __syncthreads();
    {   // layer 2: H3 = relu(H2 @ FO2^T + b2)   (H3 overlays C; C dead after sync)
        float acc[16];
        wgemm16<8,1,4>(H2, 144, FO2, 144, rg*16, cg*32, lane, acc);
        epi_store16<1,4>(acc, H3, 176, rg*16, cg*32, lane, bias2);
    }
    __syncthreads();
    {   // layer 3 + pooling reduce
        float acc[8];
        wgemm16<8,1,2>(H3, 176, FO3, 144, rg*16, cg*16, lane, acc);
#pragma unroll
        for (int nt = 0; nt < 2; nt++){
            int c = cg*16 + nt*8 + tg*2;
            float b0 = bias3[c], b1 = bias3[c+1];
            const float* a = acc + nt*4;
            float t0 = fmaxf(a[0]+b0, 0.f) + fmaxf(a[2]+b0, 0.f);
            float t1 = fmaxf(a[1]+b1, 0.f) + fmaxf(a[3]+b1, 0.f);
#pragma unroll
            for (int m = 4; m < 32; m <<= 1){
                t0 += __shfl_xor_sync(0xffffffffu, t0, m);
                t1 += __shfl_xor_sync(0xffffffffu, t1, m);
            }
            if (g == 0){ part[rg*64 + c] = t0; part[rg*64 + c + 1] = t1; }
        }
    }
    __syncthreads();
    if (tid < 64)
        pooled[tid] = part[tid] + part[64+tid] + part[128+tid] + part[192+tid];
    __syncthreads();
    if (tid < 5){
        float s = fcbs[tid];
#pragma unroll 8
        for (int j = 0; j < 64; j++)
            s = fmaf(pooled[j], fcw[j*5 + tid], s);
        out[bg*5 + tid] = s;
    }
}

// ===================== launch =====================
extern "C" void kernel_launch(void* const* d_in, const int* in_sizes, int n_in,
                              void* d_out, int out_size)
{
    const float* x       = (const float*)d_in[0];
    const float* y       = (const float*)d_in[1];
    const float* fr1_w   = (const float*)d_in[2];
    const float* fr1_b   = (const float*)d_in[3];
    const float* fr2_w   = (const float*)d_in[4];
    const float* fr2_b   = (const float*)d_in[5];
    const float* fr3_w   = (const float*)d_in[6];
    const float* fr3_b   = (const float*)d_in[7];
    const float* fr1pv_w = (const float*)d_in[8];
    const float* fr1pv_b = (const float*)d_in[9];
    const float* fr2pv_w = (const float*)d_in[10];
    const float* fr2pv_b = (const float*)d_in[11];
    const float* fr3pv_w = (const float*)d_in[12];
    const float* fr3pv_b = (const float*)d_in[13];
    const float* fo1_w   = (const float*)d_in[14];
    const float* fo1_b   = (const float*)d_in[15];
    const float* fo2_w   = (const float*)d_in[16];
    const float* fo2_b   = (const float*)d_in[17];
    const float* fo3_w   = (const float*)d_in[18];
    const float* fo3_b   = (const float*)d_in[19];
    const float* fc_w    = (const float*)d_in[20];
    const float* fc_b    = (const float*)d_in[21];
    float* out = (float*)d_out;

    cudaFuncSetAttribute(pp_kernel,  cudaFuncAttributeMaxDynamicSharedMemorySize, EP_SM);
    cudaFuncSetAttribute(pv_kernel,  cudaFuncAttributeMaxDynamicSharedMemorySize, EP_SM);
    cudaFuncSetAttribute(obj_kernel, cudaFuncAttributeMaxDynamicSharedMemorySize, OB_SM);

    init_kernel<<<304, 256>>>(x, y, fr1_w, fr1_b, fr1pv_w, fr1pv_b,
                              fr2_w, fr3_w, fr2pv_w, fr3pv_w, fo1_w, fo2_w, fo3_w);
    pp_kernel<<<152, 512, EP_SM>>>(fr2_b, fr3_b);
    pv_kernel<<<152, 512, EP_SM>>>(fr2pv_b, fr3pv_b);
    obj_kernel<<<128, 512, OB_SM>>>(x, fo1_b, fo2_b, fo3_b, fc_w, fc_b, out);
}